// round 6
// baseline (speedup 1.0000x reference)
#include <cuda_runtime.h>
#include <math.h>
#include <stdint.h>

#define Bz   2
#define Sz   2048
#define Dz   2048
#define Hz   16
#define DHz  128
#define Fz   5504
#define NTz  (Bz*Sz)      // 4096 tokens
#define BHz  (Bz*Hz)      // 32
#define ATTN_SCALE 0.08838834764831845f   // 1/sqrt(128)

// ---------------- scratch (device globals; allocation-free) ----------------
__device__ float g_h1 [(size_t)NTz*Dz];      // rounded rmsnorm out (A operand)
__device__ float g_q  [(size_t)NTz*Dz];      // q; later fp32 h3 for router
__device__ float g_k  [(size_t)NTz*Dz];      // k; later vt (transposed V)
__device__ float g_v  [(size_t)NTz*Dz];
__device__ float g_ctx[(size_t)NTz*Dz];
__device__ float g_h2 [(size_t)NTz*Dz];
__device__ float g_sc [(size_t)BHz*Sz*Sz];   // 512 MB scores/probs
__device__ float g_rs [(size_t)BHz*Sz];
__device__ float g_gate[(size_t)NTz*Fz];
__device__ float g_up  [(size_t)NTz*Fz];
__device__ int   g_choice[NTz];
// pre-rounded (TF32) weights
#define WR_Q   0
#define WR_K   4194304
#define WR_V   8388608
#define WR_O   12582912
#define WR_E1G 16777216
#define WR_E1U 28049408
#define WR_E1D 39321600
#define WR_E2G 50593792
#define WR_E2U 61865984
#define WR_E2D 73138176
#define WR_TOT 84410368
__device__ float g_wr[(size_t)WR_TOT];

// ================= TF32 MMA machinery =================
// Block tile 128x128x32, 256 threads, warp tile 32(M)x64(N).
// Both operands in smem as [row][k] pitch 36. All data pre-rounded to TF32,
// so the inner loop is pure LDS.128 + MMA (no cvt).

#define PITCH  36
#define A_FLOATS (128*PITCH)           // 4608
#define STAGE_NT (2*A_FLOATS)

__device__ __forceinline__ unsigned sptr(const void* p){ return (unsigned)__cvta_generic_to_shared(p); }
__device__ __forceinline__ void cpa16(unsigned s, const float* g){
    asm volatile("cp.async.cg.shared.global [%0], [%1], 16;\n" :: "r"(s), "l"(g));
}
__device__ __forceinline__ void cpcommit(){ asm volatile("cp.async.commit_group;\n" ::); }
__device__ __forceinline__ void cpwait1(){ asm volatile("cp.async.wait_group 1;\n" ::); }
__device__ __forceinline__ float tf32r(float f){
    unsigned u; asm("cvt.rna.tf32.f32 %0, %1;" : "=r"(u) : "f"(f)); return __uint_as_float(u);
}
__device__ __forceinline__ void mma8(float* c, unsigned a0,unsigned a1,unsigned a2,unsigned a3,
                                     unsigned b0, unsigned b1){
    asm volatile("mma.sync.aligned.m16n8k8.row.col.f32.tf32.tf32.f32 "
                 "{%0,%1,%2,%3},{%4,%5,%6,%7},{%8,%9},{%0,%1,%2,%3};\n"
                 : "+f"(c[0]),"+f"(c[1]),"+f"(c[2]),"+f"(c[3])
                 : "r"(a0),"r"(a1),"r"(a2),"r"(a3),"r"(b0),"r"(b1));
}

// load 128 rows x 32 k-cols into smem [row][k] pitch 36
__device__ __forceinline__ void load_tile_rowk(float* S, const float* G, int ld, int tid){
    const int r = tid >> 1, cb = (tid & 1) * 4;
    const float* g = G + (size_t)r * ld + cb;
    unsigned s = sptr(S) + (unsigned)(r * PITCH + cb) * 4u;
    #pragma unroll
    for (int it = 0; it < 4; it++) cpa16(s + it * 32u, g + it * 8);
}

// Virtual-K permutation: chunk c, thread tg supplies physical k = tg*8+c (+4).
// Each thread's 8 k-values per row are two contiguous uint4s at [row][tg*8].
__device__ __forceinline__ void compute_nt(const float* __restrict__ Asf, const float* __restrict__ Bsf,
                                           float acc[2][8][4], int warpM, int warpN, int lane){
    const unsigned* As = (const unsigned*)Asf;
    const unsigned* Bs = (const unsigned*)Bsf;
    const int gi = lane >> 2, tg = lane & 3;
    unsigned a[4][8];                    // rows: base+gi, +8, +16, +24
    const int r0 = warpM*32 + gi;
    #pragma unroll
    for (int r = 0; r < 4; r++){
        const unsigned* p = As + (r0 + r*8)*PITCH + tg*8;
        *(uint4*)&a[r][0] = *(const uint4*)p;
        *(uint4*)&a[r][4] = *(const uint4*)(p+4);
    }
    #pragma unroll
    for (int j = 0; j < 8; j++){
        const int n = warpN*64 + j*8 + gi;
        unsigned b[8];
        const unsigned* p = Bs + n*PITCH + tg*8;
        *(uint4*)&b[0] = *(const uint4*)p;
        *(uint4*)&b[4] = *(const uint4*)(p+4);
        #pragma unroll
        for (int c = 0; c < 4; c++){
            mma8(acc[0][j], a[0][c], a[1][c], a[0][c+4], a[1][c+4], b[c], b[c+4]);
            mma8(acc[1][j], a[2][c], a[3][c], a[2][c+4], a[3][c+4], b[c], b[c+4]);
        }
    }
}

// ---------- generic NT: C[M,N] = A[M,K] * B[N,K]^T (+bias)(+add), A/B pre-TF32 ----------
extern __shared__ float smem[];
__global__ __launch_bounds__(256, 2) void tf32_gemm_nt(
    const float* __restrict__ A, const float* __restrict__ B,
    float* __restrict__ C, const float* __restrict__ bias,
    const float* __restrict__ add, int M, int N, int K)
{
    const int tid = threadIdx.x, lane = tid & 31, warp = tid >> 5;
    const int warpM = warp & 3, warpN = warp >> 2;
    const int bm = blockIdx.y, bn = blockIdx.x;
    const float* Ag = A + (size_t)bm * 128 * K;
    const float* Bg = B + (size_t)bn * 128 * K;
    float acc[2][8][4];
    #pragma unroll
    for (int i=0;i<2;i++) for (int j=0;j<8;j++) for (int c=0;c<4;c++) acc[i][j][c]=0.f;

    const int T = K / 32;
    load_tile_rowk(smem, Ag, K, tid);
    load_tile_rowk(smem + A_FLOATS, Bg, K, tid);
    cpcommit();
    if (T > 1){
        load_tile_rowk(smem + STAGE_NT, Ag + 32, K, tid);
        load_tile_rowk(smem + STAGE_NT + A_FLOATS, Bg + 32, K, tid);
    }
    cpcommit();
    for (int t = 0; t < T; t++){
        cpwait1(); __syncthreads();
        const float* Sa = smem + (t & 1) * STAGE_NT;
        compute_nt(Sa, Sa + A_FLOATS, acc, warpM, warpN, lane);
        __syncthreads();
        if (t + 2 < T){
            float* Sd = smem + (t & 1) * STAGE_NT;
            load_tile_rowk(Sd, Ag + (t+2)*32, K, tid);
            load_tile_rowk(Sd + A_FLOATS, Bg + (t+2)*32, K, tid);
        }
        cpcommit();
    }
    const int gi = lane >> 2, tg = lane & 3;
    #pragma unroll
    for (int i = 0; i < 2; i++){
        const int row = bm*128 + warpM*32 + i*16 + gi;
        #pragma unroll
        for (int j = 0; j < 8; j++){
            const int col = bn*128 + warpN*64 + j*8 + tg*2;
            float2 v0 = make_float2(acc[i][j][0], acc[i][j][1]);
            float2 v1 = make_float2(acc[i][j][2], acc[i][j][3]);
            if (bias){
                const float b0 = bias[col], b1 = bias[col+1];
                v0.x += b0; v0.y += b1; v1.x += b0; v1.y += b1;
            }
            if (add){
                float2 r0 = *(const float2*)&add[(size_t)row * N + col];
                float2 r1 = *(const float2*)&add[(size_t)(row+8) * N + col];
                v0.x += r0.x; v0.y += r0.y; v1.x += r1.x; v1.y += r1.y;
            }
            *(float2*)&C[(size_t)row * N + col]     = v0;
            *(float2*)&C[(size_t)(row+8) * N + col] = v1;
        }
    }
}

// ---------- attention scores: causal, scaled ----------
__global__ __launch_bounds__(256, 2) void tf32_scores(
    const float* __restrict__ Q, const float* __restrict__ Km, float* __restrict__ Sc)
{
    const int z = blockIdx.z, b = z >> 4, h = z & 15;
    const int bm = blockIdx.y, bn = blockIdx.x;
    const int tid = threadIdx.x;
    float* Cb = Sc + (size_t)z * Sz * Sz;

    if (bn > bm){
        const float4 m4 = make_float4(-1e30f,-1e30f,-1e30f,-1e30f);
        #pragma unroll
        for (int it = 0; it < 16; it++){
            const int idx = it * 256 + tid;
            const int r = idx >> 5, c = (idx & 31) * 4;
            *(float4*)&Cb[(size_t)(bm*128 + r) * Sz + bn*128 + c] = m4;
        }
        return;
    }
    const int lane = tid & 31, warp = tid >> 5;
    const int warpM = warp & 3, warpN = warp >> 2;
    const float* Ag = Q  + (size_t)(b*Sz + bm*128) * Dz + (size_t)h * DHz;
    const float* Bg = Km + (size_t)(b*Sz + bn*128) * Dz + (size_t)h * DHz;
    float acc[2][8][4];
    #pragma unroll
    for (int i=0;i<2;i++) for (int j=0;j<8;j++) for (int c=0;c<4;c++) acc[i][j][c]=0.f;

    const int T = DHz / 32;
    load_tile_rowk(smem, Ag, Dz, tid);
    load_tile_rowk(smem + A_FLOATS, Bg, Dz, tid);
    cpcommit();
    load_tile_rowk(smem + STAGE_NT, Ag + 32, Dz, tid);
    load_tile_rowk(smem + STAGE_NT + A_FLOATS, Bg + 32, Dz, tid);
    cpcommit();
    for (int t = 0; t < T; t++){
        cpwait1(); __syncthreads();
        const float* Sa = smem + (t & 1) * STAGE_NT;
        compute_nt(Sa, Sa + A_FLOATS, acc, warpM, warpN, lane);
        __syncthreads();
        if (t + 2 < T){
            float* Sd = smem + (t & 1) * STAGE_NT;
            load_tile_rowk(Sd, Ag + (t+2)*32, Dz, tid);
            load_tile_rowk(Sd + A_FLOATS, Bg + (t+2)*32, Dz, tid);
        }
        cpcommit();
    }
    const int gi = lane >> 2, tg = lane & 3;
    #pragma unroll
    for (int i = 0; i < 2; i++){
        const int row0 = bm*128 + warpM*32 + i*16 + gi;
        #pragma unroll
        for (int j = 0; j < 8; j++){
            const int col = bn*128 + warpN*64 + j*8 + tg*2;
            float2 v0, v1;
            v0.x = (col   <= row0  ) ? acc[i][j][0]*ATTN_SCALE : -1e30f;
            v0.y = (col+1 <= row0  ) ? acc[i][j][1]*ATTN_SCALE : -1e30f;
            v1.x = (col   <= row0+8) ? acc[i][j][2]*ATTN_SCALE : -1e30f;
            v1.y = (col+1 <= row0+8) ? acc[i][j][3]*ATTN_SCALE : -1e30f;
            *(float2*)&Cb[(size_t)row0 * Sz + col]     = v0;
            *(float2*)&Cb[(size_t)(row0+8) * Sz + col] = v1;
        }
    }
}

// ---------- attention ctx: Cx = P Vt^T (NT form), causal K-trim, normalized, rounded ----------
__global__ __launch_bounds__(256, 2) void tf32_ctx(
    const float* __restrict__ P, const float* __restrict__ Vt,
    const float* __restrict__ rowsum, float* __restrict__ Cx)
{
    const int z = blockIdx.z, b = z >> 4, h = z & 15;
    const int bm = blockIdx.y;
    const int tid = threadIdx.x, lane = tid & 31, warp = tid >> 5;
    const int warpM = warp & 3, warpN = warp >> 2;
    const float* Ag = P + (size_t)z * Sz * Sz + (size_t)bm * 128 * Sz;  // pitch Sz
    const float* Bg = Vt + (size_t)z * 128 * Sz;                        // [dim][token] pitch Sz
    float acc[2][8][4];
    #pragma unroll
    for (int i=0;i<2;i++) for (int j=0;j<8;j++) for (int c=0;c<4;c++) acc[i][j][c]=0.f;

    const int T = (bm + 1) * 4;
    load_tile_rowk(smem, Ag, Sz, tid);
    load_tile_rowk(smem + A_FLOATS, Bg, Sz, tid);
    cpcommit();
    if (T > 1){
        load_tile_rowk(smem + STAGE_NT, Ag + 32, Sz, tid);
        load_tile_rowk(smem + STAGE_NT + A_FLOATS, Bg + 32, Sz, tid);
    }
    cpcommit();
    for (int t = 0; t < T; t++){
        cpwait1(); __syncthreads();
        const float* Sa = smem + (t & 1) * STAGE_NT;
        compute_nt(Sa, Sa + A_FLOATS, acc, warpM, warpN, lane);
        __syncthreads();
        if (t + 2 < T){
            float* Sd = smem + (t & 1) * STAGE_NT;
            load_tile_rowk(Sd, Ag + (t+2)*32, Sz, tid);
            load_tile_rowk(Sd + A_FLOATS, Bg + (t+2)*32, Sz, tid);
        }
        cpcommit();
    }
    const int gi = lane >> 2, tg = lane & 3;
    #pragma unroll
    for (int i = 0; i < 2; i++){
        const int rloc = bm*128 + warpM*32 + i*16 + gi;
        const float inv0 = 1.f / rowsum[(size_t)z * Sz + rloc];
        const float inv1 = 1.f / rowsum[(size_t)z * Sz + rloc + 8];
        const size_t row0 = (size_t)(b*Sz) + rloc;
        #pragma unroll
        for (int j = 0; j < 8; j++){
            const int col = h*DHz + warpN*64 + j*8 + tg*2;
            float2 v0 = make_float2(tf32r(acc[i][j][0]*inv0), tf32r(acc[i][j][1]*inv0));
            float2 v1 = make_float2(tf32r(acc[i][j][2]*inv1), tf32r(acc[i][j][3]*inv1));
            *(float2*)&Cx[row0 * Dz + col]     = v0;
            *(float2*)&Cx[(row0+8) * Dz + col] = v1;
        }
    }
}

// ================= helpers / elementwise =================
__global__ __launch_bounds__(256) void tf32_round_kernel(
    const float* __restrict__ src, float* __restrict__ dst, int n4)
{
    const int i = blockIdx.x * 256 + threadIdx.x;
    if (i >= n4) return;
    float4 v = *(const float4*)(src + (size_t)i*4);
    v.x = tf32r(v.x); v.y = tf32r(v.y); v.z = tf32r(v.z); v.w = tf32r(v.w);
    *(float4*)(dst + (size_t)i*4) = v;
}

// transpose v[token][Dz] -> vt[(b*16+h)*128+dh][token_in_batch], rounded
__global__ __launch_bounds__(256) void transpose_v(const float* __restrict__ v, float* __restrict__ vt)
{
    __shared__ float tile[32][33];
    const int tid = threadIdx.x;
    const int d0 = blockIdx.x * 32, t0 = blockIdx.y * 32;
    const int tx = tid & 31, ty = tid >> 5;
    #pragma unroll
    for (int it = 0; it < 4; it++){
        const int tok = t0 + ty + it*8;
        tile[ty + it*8][tx] = v[(size_t)tok * Dz + d0 + tx];
    }
    __syncthreads();
    #pragma unroll
    for (int it = 0; it < 4; it++){
        const int dh_loc = ty + it*8;
        const int gd = d0 + dh_loc;
        const int tok = t0 + tx;
        const int bb = tok >> 11, tin = tok & 2047;
        vt[((size_t)(bb*16) * 128 + gd) * Sz + tin] = tf32r(tile[tx][dh_loc]);
    }
}

__global__ __launch_bounds__(256) void rmsnorm_kernel(
    const float* __restrict__ x, const float* __restrict__ w,
    float* __restrict__ out, float* __restrict__ out_raw)
{
    const int row = blockIdx.x;
    const float* xr = x + (size_t)row * Dz;
    float* orow = out + (size_t)row * Dz;
    const int tid = threadIdx.x;
    float ss = 0.f;
    #pragma unroll
    for (int i = tid*4; i < Dz; i += 1024) {
        float4 v = *(const float4*)(xr + i);
        ss += v.x*v.x + v.y*v.y + v.z*v.z + v.w*v.w;
    }
    __shared__ float red[256];
    red[tid] = ss; __syncthreads();
    for (int s = 128; s > 0; s >>= 1) { if (tid < s) red[tid] += red[tid+s]; __syncthreads(); }
    const float scale = rsqrtf(red[0] / (float)Dz + 1e-6f);
    #pragma unroll
    for (int i = tid*4; i < Dz; i += 1024) {
        float4 v = *(const float4*)(xr + i);
        float4 ww = *(const float4*)(w + i);
        float4 o;
        o.x = v.x*scale*ww.x; o.y = v.y*scale*ww.y;
        o.z = v.z*scale*ww.z; o.w = v.w*scale*ww.w;
        if (out_raw) *(float4*)(out_raw + (size_t)row * Dz + i) = o;
        o.x = tf32r(o.x); o.y = tf32r(o.y); o.z = tf32r(o.z); o.w = tf32r(o.w);
        *(float4*)(orow + i) = o;
    }
}

__global__ __launch_bounds__(256) void rope_kernel(float* __restrict__ q, float* __restrict__ k)
{
    const size_t idx = (size_t)blockIdx.x * 256 + threadIdx.x;
    if (idx >= (size_t)NTz * Hz * 64) return;
    const int    j    = (int)(idx & 63);
    const size_t th   = idx >> 6;
    const int    head = (int)(th & 15);
    const size_t tok  = th >> 4;
    const int    s    = (int)(tok & (Sz - 1));
    const double inv  = exp(-(double)(2*j) / 128.0 * 9.210340371976184);
    const double ang  = (double)s * inv;
    const float  c  = (float)cos(ang);
    const float  sn = (float)sin(ang);
    const size_t base = tok * (size_t)Dz + (size_t)head * DHz + j;
    float q1 = q[base], q2 = q[base + 64];
    q[base]      = tf32r(q1*c - q2*sn);
    q[base + 64] = tf32r(q2*c + q1*sn);
    float k1 = k[base], k2 = k[base + 64];
    k[base]      = tf32r(k1*c - k2*sn);
    k[base + 64] = tf32r(k2*c + k1*sn);
}

__global__ __launch_bounds__(256) void softmax_kernel(float* __restrict__ Sc, float* __restrict__ rowsum)
{
    const size_t row = blockIdx.x;
    float* p = Sc + row * (size_t)Sz;
    const int tid = threadIdx.x;
    float m = -1e30f;
    #pragma unroll
    for (int i = tid*4; i < Sz; i += 1024) {
        float4 v = *(const float4*)(p + i);
        m = fmaxf(m, fmaxf(fmaxf(v.x, v.y), fmaxf(v.z, v.w)));
    }
    __shared__ float red[256];
    red[tid] = m; __syncthreads();
    for (int s = 128; s > 0; s >>= 1) { if (tid < s) red[tid] = fmaxf(red[tid], red[tid+s]); __syncthreads(); }
    m = red[0];
    __syncthreads();
    float sum = 0.f;
    #pragma unroll
    for (int i = tid*4; i < Sz; i += 1024) {
        float4 v = *(const float4*)(p + i);
        v.x = tf32r(expf(v.x - m)); v.y = tf32r(expf(v.y - m));
        v.z = tf32r(expf(v.z - m)); v.w = tf32r(expf(v.w - m));
        sum += v.x + v.y + v.z + v.w;
        *(float4*)(p + i) = v;
    }
    red[tid] = sum; __syncthreads();
    for (int s = 128; s > 0; s >>= 1) { if (tid < s) red[tid] += red[tid+s]; __syncthreads(); }
    if (tid == 0) rowsum[row] = red[0];
}

__global__ __launch_bounds__(256) void router_kernel(
    const float* __restrict__ h, const float* __restrict__ rw,
    const float* __restrict__ rb, int* __restrict__ choice)
{
    const int t = blockIdx.x;
    const float* xr = h + (size_t)t * Dz;
    const int tid = threadIdx.x;
    float s0 = 0.f, s1 = 0.f;
    #pragma unroll
    for (int i = tid*4; i < Dz; i += 1024) {
        float4 v  = *(const float4*)(xr + i);
        float4 w0 = *(const float4*)(rw + i);
        float4 w1 = *(const float4*)(rw + Dz + i);
        s0 += v.x*w0.x + v.y*w0.y + v.z*w0.z + v.w*w0.w;
        s1 += v.x*w1.x + v.y*w1.y + v.z*w1.z + v.w*w1.w;
    }
    __shared__ float r0[256], r1[256];
    r0[tid] = s0; r1[tid] = s1; __syncthreads();
    for (int s = 128; s > 0; s >>= 1) {
        if (tid < s) { r0[tid] += r0[tid+s]; r1[tid] += r1[tid+s]; }
        __syncthreads();
    }
    if (tid == 0) {
        const float l0 = r0[0] + rb[0], l1 = r1[0] + rb[1];
        choice[t] = (l1 > l0) ? 1 : 0;
    }
}

__global__ __launch_bounds__(256) void act_kernel(
    float* __restrict__ gate, const float* __restrict__ up,
    const int* __restrict__ choice, int e)
{
    const int f = blockIdx.x * 256 + threadIdx.x;
    if (f >= Fz) return;
    const int tok = blockIdx.y;
    const size_t idx = (size_t)tok * Fz + f;
    if (choice[tok] == e) {
        const float g = gate[idx];
        gate[idx] = tf32r((g / (1.f + expf(-g))) * up[idx]);
    } else {
        gate[idx] = 0.f;
    }
}

// ================= launch =================
extern "C" void kernel_launch(void* const* d_in, const int* in_sizes, int n_in,
                              void* d_out, int out_size)
{
    const float* x    = (const float*)d_in[0];
    const float* ln1w = (const float*)d_in[1];
    const float* wq   = (const float*)d_in[2];
    const float* bq   = (const float*)d_in[3];
    const float* wk   = (const float*)d_in[4];
    const float* bk   = (const float*)d_in[5];
    const float* wv   = (const float*)d_in[6];
    const float* bv   = (const float*)d_in[7];
    const float* wo   = (const float*)d_in[8];
    const float* ln2w = (const float*)d_in[9];
    const float* e1g  = (const float*)d_in[10];
    const float* e1u  = (const float*)d_in[11];
    const float* e1d  = (const float*)d_in[12];
    const float* e2g  = (const float*)d_in[13];
    const float* e2u  = (const float*)d_in[14];
    const float* e2d  = (const float*)d_in[15];
    const float* rw   = (const float*)d_in[16];
    const float* rb   = (const float*)d_in[17];
    float* out = (float*)d_out;

    float *h1, *q, *k, *v, *ctx, *h2, *sc, *rs, *gate, *up, *wr;
    int* choice;
    cudaGetSymbolAddress((void**)&h1,  g_h1);
    cudaGetSymbolAddress((void**)&q,   g_q);
    cudaGetSymbolAddress((void**)&k,   g_k);
    cudaGetSymbolAddress((void**)&v,   g_v);
    cudaGetSymbolAddress((void**)&ctx, g_ctx);
    cudaGetSymbolAddress((void**)&h2,  g_h2);
    cudaGetSymbolAddress((void**)&sc,  g_sc);
    cudaGetSymbolAddress((void**)&rs,  g_rs);
    cudaGetSymbolAddress((void**)&gate, g_gate);
    cudaGetSymbolAddress((void**)&up,   g_up);
    cudaGetSymbolAddress((void**)&wr,   g_wr);
    cudaGetSymbolAddress((void**)&choice, g_choice);

    const int SMEM_NT = STAGE_NT * 2 * 4;   // 73728 B
    cudaFuncSetAttribute(tf32_gemm_nt, cudaFuncAttributeMaxDynamicSharedMemorySize, SMEM_NT);
    cudaFuncSetAttribute(tf32_scores,  cudaFuncAttributeMaxDynamicSharedMemorySize, SMEM_NT);
    cudaFuncSetAttribute(tf32_ctx,     cudaFuncAttributeMaxDynamicSharedMemorySize, SMEM_NT);

    // --- weight pre-rounding (TF32) ---
    #define RND(src, off, n) tf32_round_kernel<<<((n)/4+255)/256, 256>>>(src, wr + (size_t)(off), (n)/4)
    RND(wq,  WR_Q,   Dz*Dz);  RND(wk,  WR_K,   Dz*Dz);
    RND(wv,  WR_V,   Dz*Dz);  RND(wo,  WR_O,   Dz*Dz);
    RND(e1g, WR_E1G, Fz*Dz);  RND(e1u, WR_E1U, Fz*Dz);  RND(e1d, WR_E1D, Fz*Dz);
    RND(e2g, WR_E2G, Fz*Dz);  RND(e2u, WR_E2U, Fz*Dz);  RND(e2d, WR_E2D, Fz*Dz);
    #undef RND

    // --- attention block ---
    rmsnorm_kernel<<<NTz, 256>>>(x, ln1w, h1, nullptr);
    tf32_gemm_nt<<<dim3(Dz/128, NTz/128), 256, SMEM_NT>>>(h1, wr+WR_Q, q, bq, nullptr, NTz, Dz, Dz);
    tf32_gemm_nt<<<dim3(Dz/128, NTz/128), 256, SMEM_NT>>>(h1, wr+WR_K, k, bk, nullptr, NTz, Dz, Dz);
    tf32_gemm_nt<<<dim3(Dz/128, NTz/128), 256, SMEM_NT>>>(h1, wr+WR_V, v, bv, nullptr, NTz, Dz, Dz);
    rope_kernel<<<(NTz*Hz*64)/256, 256>>>(q, k);
    tf32_scores<<<dim3(Sz/128, Sz/128, BHz), 256, SMEM_NT>>>(q, k, sc);
    // after scores has consumed k, reuse its memory as vt
    float* vt = k;
    transpose_v<<<dim3(Dz/32, NTz/32), 256>>>(v, vt);
    softmax_kernel<<<BHz*Sz, 256>>>(sc, rs);
    tf32_ctx<<<dim3(1, Sz/128, BHz), 256, SMEM_NT>>>(sc, vt, rs, ctx);
    tf32_gemm_nt<<<dim3(Dz/128, NTz/128), 256, SMEM_NT>>>(ctx, wr+WR_O, h2, nullptr, x, NTz, Dz, Dz);

    // --- MoE block --- (q buffer reused as fp32 h3 for the router)
    rmsnorm_kernel<<<NTz, 256>>>(h2, ln2w, h1, q);
    router_kernel<<<NTz, 256>>>(q, rw, rb, choice);

    tf32_gemm_nt<<<dim3(Fz/128, NTz/128), 256, SMEM_NT>>>(h1, wr+WR_E1G, gate, nullptr, nullptr, NTz, Fz, Dz);
    tf32_gemm_nt<<<dim3(Fz/128, NTz/128), 256, SMEM_NT>>>(h1, wr+WR_E1U, up,   nullptr, nullptr, NTz, Fz, Dz);
    act_kernel<<<dim3((Fz+255)/256, NTz), 256>>>(gate, up, choice, 0);
    tf32_gemm_nt<<<dim3(Dz/128, NTz/128), 256, SMEM_NT>>>(gate, wr+WR_E1D, out, nullptr, h2, NTz, Dz, Fz);

    tf32_gemm_nt<<<dim3(Fz/128, NTz/128), 256, SMEM_NT>>>(h1, wr+WR_E2G, gate, nullptr, nullptr, NTz, Fz, Dz);
    tf32_gemm_nt<<<dim3(Fz/128, NTz/128), 256, SMEM_NT>>>(h1, wr+WR_E2U, up,   nullptr, nullptr, NTz, Fz, Dz);
    act_kernel<<<dim3((Fz+255)/256, NTz), 256>>>(gate, up, choice, 1);
    tf32_gemm_nt<<<dim3(Dz/128, NTz/128), 256, SMEM_NT>>>(gate, wr+WR_E2D, out, nullptr, out, NTz, Dz, Fz);
}

// round 7
// speedup vs baseline: 1.1097x; 1.1097x over previous
#include <cuda_runtime.h>
#include <math.h>
#include <stdint.h>

#define Bz   2
#define Sz   2048
#define Dz   2048
#define Hz   16
#define DHz  128
#define Fz   5504
#define NTz  (Bz*Sz)      // 4096 tokens
#define BHz  (Bz*Hz)      // 32
#define ATTN_SCALE 0.08838834764831845f   // 1/sqrt(128)

// ---------------- scratch (device globals; allocation-free) ----------------
__device__ float g_h1 [(size_t)NTz*Dz];      // rounded rmsnorm out (A operand)
__device__ float g_q  [(size_t)NTz*Dz];      // q; later fp32 h3 for router
__device__ float g_k  [(size_t)NTz*Dz];      // k; later vt (transposed V)
__device__ float g_v  [(size_t)NTz*Dz];
__device__ float g_ctx[(size_t)NTz*Dz];
__device__ float g_h2 [(size_t)NTz*Dz];
__device__ float g_sc [(size_t)BHz*Sz*Sz];   // 512 MB scores/probs
__device__ float g_rs [(size_t)BHz*Sz];
__device__ float g_gate[(size_t)NTz*Fz];
__device__ float g_up  [(size_t)NTz*Fz];
__device__ int   g_choice[NTz];
// pre-rounded (TF32) weights
#define WR_Q   0
#define WR_K   4194304
#define WR_V   8388608
#define WR_O   12582912
#define WR_E1G 16777216
#define WR_E1U 28049408
#define WR_E1D 39321600
#define WR_E2G 50593792
#define WR_E2U 61865984
#define WR_E2D 73138176
#define WR_TOT 84410368
__device__ float g_wr[(size_t)WR_TOT];

// ================= TF32 MMA machinery =================
// Block tile 128x128x32, 256 threads, warp tile 32(M)x64(N).
// Operands in smem [row][k] pitch 36, pre-rounded to TF32 -> inner loop is
// pure LDS.128 + MMA. Two k-half passes keep live regs ~100 (< 128 cap).

#define PITCH  36
#define A_FLOATS (128*PITCH)           // 4608
#define STAGE_NT (2*A_FLOATS)

__device__ __forceinline__ unsigned sptr(const void* p){ return (unsigned)__cvta_generic_to_shared(p); }
__device__ __forceinline__ void cpa16(unsigned s, const float* g){
    asm volatile("cp.async.cg.shared.global [%0], [%1], 16;\n" :: "r"(s), "l"(g));
}
__device__ __forceinline__ void cpcommit(){ asm volatile("cp.async.commit_group;\n" ::); }
__device__ __forceinline__ void cpwait1(){ asm volatile("cp.async.wait_group 1;\n" ::); }
__device__ __forceinline__ float tf32r(float f){
    unsigned u; asm("cvt.rna.tf32.f32 %0, %1;" : "=r"(u) : "f"(f)); return __uint_as_float(u);
}
__device__ __forceinline__ void mma8(float* c, unsigned a0,unsigned a1,unsigned a2,unsigned a3,
                                     unsigned b0, unsigned b1){
    asm volatile("mma.sync.aligned.m16n8k8.row.col.f32.tf32.tf32.f32 "
                 "{%0,%1,%2,%3},{%4,%5,%6,%7},{%8,%9},{%0,%1,%2,%3};\n"
                 : "+f"(c[0]),"+f"(c[1]),"+f"(c[2]),"+f"(c[3])
                 : "r"(a0),"r"(a1),"r"(a2),"r"(a3),"r"(b0),"r"(b1));
}

// load 128 rows x 32 k-cols into smem [row][k] pitch 36
__device__ __forceinline__ void load_tile_rowk(float* S, const float* G, int ld, int tid){
    const int r = tid >> 1, cb = (tid & 1) * 4;
    const float* g = G + (size_t)r * ld + cb;
    unsigned s = sptr(S) + (unsigned)(r * PITCH + cb) * 4u;
    #pragma unroll
    for (int it = 0; it < 4; it++) cpa16(s + it * 32u, g + it * 8);
}

// Virtual-K bijection: MMA chunk (half, c), thread tg supplies physical
// k0 = tg*8 + half*4 + 2c, k1 = k0 + 1. Applied identically to A and B,
// so the dot product is exact. Each thread's half needs ONE uint4 per row.
__device__ __forceinline__ void compute_nt(const float* __restrict__ Asf, const float* __restrict__ Bsf,
                                           float acc[2][8][4], int warpM, int warpN, int lane){
    const unsigned* As = (const unsigned*)Asf;
    const unsigned* Bs = (const unsigned*)Bsf;
    const int gi = lane >> 2, tg = lane & 3;
    const int r0 = warpM*32 + gi;
    #pragma unroll
    for (int half = 0; half < 2; half++){
        unsigned a[4][4];
        #pragma unroll
        for (int r = 0; r < 4; r++)
            *(uint4*)a[r] = *(const uint4*)(As + (r0 + r*8)*PITCH + tg*8 + half*4);
        #pragma unroll
        for (int j = 0; j < 8; j++){
            const int n = warpN*64 + j*8 + gi;
            unsigned b[4];
            *(uint4*)b = *(const uint4*)(Bs + n*PITCH + tg*8 + half*4);
            #pragma unroll
            for (int c = 0; c < 2; c++){
                mma8(acc[0][j], a[0][2*c], a[1][2*c], a[0][2*c+1], a[1][2*c+1], b[2*c], b[2*c+1]);
                mma8(acc[1][j], a[2][2*c], a[3][2*c], a[2][2*c+1], a[3][2*c+1], b[2*c], b[2*c+1]);
            }
        }
    }
}

// ---------- generic NT: C[M,N] = A[M,K] * B[N,K]^T (+bias)(+add), A/B pre-TF32 ----------
extern __shared__ float smem[];
__global__ __launch_bounds__(256, 2) void tf32_gemm_nt(
    const float* __restrict__ A, const float* __restrict__ B,
    float* __restrict__ C, const float* __restrict__ bias,
    const float* __restrict__ add, int M, int N, int K)
{
    const int tid = threadIdx.x, lane = tid & 31, warp = tid >> 5;
    const int warpM = warp & 3, warpN = warp >> 2;
    const int bm = blockIdx.y, bn = blockIdx.x;
    const float* Ag = A + (size_t)bm * 128 * K;
    const float* Bg = B + (size_t)bn * 128 * K;
    float acc[2][8][4];
    #pragma unroll
    for (int i=0;i<2;i++) for (int j=0;j<8;j++) for (int c=0;c<4;c++) acc[i][j][c]=0.f;

    const int T = K / 32;
    load_tile_rowk(smem, Ag, K, tid);
    load_tile_rowk(smem + A_FLOATS, Bg, K, tid);
    cpcommit();
    if (T > 1){
        load_tile_rowk(smem + STAGE_NT, Ag + 32, K, tid);
        load_tile_rowk(smem + STAGE_NT + A_FLOATS, Bg + 32, K, tid);
    }
    cpcommit();
    for (int t = 0; t < T; t++){
        cpwait1(); __syncthreads();
        const float* Sa = smem + (t & 1) * STAGE_NT;
        compute_nt(Sa, Sa + A_FLOATS, acc, warpM, warpN, lane);
        __syncthreads();
        if (t + 2 < T){
            float* Sd = smem + (t & 1) * STAGE_NT;
            load_tile_rowk(Sd, Ag + (t+2)*32, K, tid);
            load_tile_rowk(Sd + A_FLOATS, Bg + (t+2)*32, K, tid);
        }
        cpcommit();
    }
    const int gi = lane >> 2, tg = lane & 3;
    #pragma unroll
    for (int i = 0; i < 2; i++){
        const int row = bm*128 + warpM*32 + i*16 + gi;
        #pragma unroll
        for (int j = 0; j < 8; j++){
            const int col = bn*128 + warpN*64 + j*8 + tg*2;
            float2 v0 = make_float2(acc[i][j][0], acc[i][j][1]);
            float2 v1 = make_float2(acc[i][j][2], acc[i][j][3]);
            if (bias){
                const float b0 = bias[col], b1 = bias[col+1];
                v0.x += b0; v0.y += b1; v1.x += b0; v1.y += b1;
            }
            if (add){
                float2 r0 = *(const float2*)&add[(size_t)row * N + col];
                float2 r1 = *(const float2*)&add[(size_t)(row+8) * N + col];
                v0.x += r0.x; v0.y += r0.y; v1.x += r1.x; v1.y += r1.y;
            }
            *(float2*)&C[(size_t)row * N + col]     = v0;
            *(float2*)&C[(size_t)(row+8) * N + col] = v1;
        }
    }
}

// ---------- attention scores: causal, scaled ----------
__global__ __launch_bounds__(256, 2) void tf32_scores(
    const float* __restrict__ Q, const float* __restrict__ Km, float* __restrict__ Sc)
{
    const int z = blockIdx.z, b = z >> 4, h = z & 15;
    const int bm = blockIdx.y, bn = blockIdx.x;
    const int tid = threadIdx.x;
    float* Cb = Sc + (size_t)z * Sz * Sz;

    if (bn > bm){
        const float4 m4 = make_float4(-1e30f,-1e30f,-1e30f,-1e30f);
        #pragma unroll
        for (int it = 0; it < 16; it++){
            const int idx = it * 256 + tid;
            const int r = idx >> 5, c = (idx & 31) * 4;
            *(float4*)&Cb[(size_t)(bm*128 + r) * Sz + bn*128 + c] = m4;
        }
        return;
    }
    const int lane = tid & 31, warp = tid >> 5;
    const int warpM = warp & 3, warpN = warp >> 2;
    const float* Ag = Q  + (size_t)(b*Sz + bm*128) * Dz + (size_t)h * DHz;
    const float* Bg = Km + (size_t)(b*Sz + bn*128) * Dz + (size_t)h * DHz;
    float acc[2][8][4];
    #pragma unroll
    for (int i=0;i<2;i++) for (int j=0;j<8;j++) for (int c=0;c<4;c++) acc[i][j][c]=0.f;

    const int T = DHz / 32;
    load_tile_rowk(smem, Ag, Dz, tid);
    load_tile_rowk(smem + A_FLOATS, Bg, Dz, tid);
    cpcommit();
    load_tile_rowk(smem + STAGE_NT, Ag + 32, Dz, tid);
    load_tile_rowk(smem + STAGE_NT + A_FLOATS, Bg + 32, Dz, tid);
    cpcommit();
    for (int t = 0; t < T; t++){
        cpwait1(); __syncthreads();
        const float* Sa = smem + (t & 1) * STAGE_NT;
        compute_nt(Sa, Sa + A_FLOATS, acc, warpM, warpN, lane);
        __syncthreads();
        if (t + 2 < T){
            float* Sd = smem + (t & 1) * STAGE_NT;
            load_tile_rowk(Sd, Ag + (t+2)*32, Dz, tid);
            load_tile_rowk(Sd + A_FLOATS, Bg + (t+2)*32, Dz, tid);
        }
        cpcommit();
    }
    const int gi = lane >> 2, tg = lane & 3;
    #pragma unroll
    for (int i = 0; i < 2; i++){
        const int row0 = bm*128 + warpM*32 + i*16 + gi;
        #pragma unroll
        for (int j = 0; j < 8; j++){
            const int col = bn*128 + warpN*64 + j*8 + tg*2;
            float2 v0, v1;
            v0.x = (col   <= row0  ) ? acc[i][j][0]*ATTN_SCALE : -1e30f;
            v0.y = (col+1 <= row0  ) ? acc[i][j][1]*ATTN_SCALE : -1e30f;
            v1.x = (col   <= row0+8) ? acc[i][j][2]*ATTN_SCALE : -1e30f;
            v1.y = (col+1 <= row0+8) ? acc[i][j][3]*ATTN_SCALE : -1e30f;
            *(float2*)&Cb[(size_t)row0 * Sz + col]     = v0;
            *(float2*)&Cb[(size_t)(row0+8) * Sz + col] = v1;
        }
    }
}

// ---------- attention ctx: Cx = P Vt^T (NT form), causal K-trim, normalized, rounded ----------
__global__ __launch_bounds__(256, 2) void tf32_ctx(
    const float* __restrict__ P, const float* __restrict__ Vt,
    const float* __restrict__ rowsum, float* __restrict__ Cx)
{
    const int z = blockIdx.z, b = z >> 4, h = z & 15;
    const int bm = blockIdx.y;
    const int tid = threadIdx.x, lane = tid & 31, warp = tid >> 5;
    const int warpM = warp & 3, warpN = warp >> 2;
    const float* Ag = P + (size_t)z * Sz * Sz + (size_t)bm * 128 * Sz;  // pitch Sz
    const float* Bg = Vt + (size_t)z * 128 * Sz;                        // [dim][token] pitch Sz
    float acc[2][8][4];
    #pragma unroll
    for (int i=0;i<2;i++) for (int j=0;j<8;j++) for (int c=0;c<4;c++) acc[i][j][c]=0.f;

    const int T = (bm + 1) * 4;
    load_tile_rowk(smem, Ag, Sz, tid);
    load_tile_rowk(smem + A_FLOATS, Bg, Sz, tid);
    cpcommit();
    if (T > 1){
        load_tile_rowk(smem + STAGE_NT, Ag + 32, Sz, tid);
        load_tile_rowk(smem + STAGE_NT + A_FLOATS, Bg + 32, Sz, tid);
    }
    cpcommit();
    for (int t = 0; t < T; t++){
        cpwait1(); __syncthreads();
        const float* Sa = smem + (t & 1) * STAGE_NT;
        compute_nt(Sa, Sa + A_FLOATS, acc, warpM, warpN, lane);
        __syncthreads();
        if (t + 2 < T){
            float* Sd = smem + (t & 1) * STAGE_NT;
            load_tile_rowk(Sd, Ag + (t+2)*32, Sz, tid);
            load_tile_rowk(Sd + A_FLOATS, Bg + (t+2)*32, Sz, tid);
        }
        cpcommit();
    }
    const int gi = lane >> 2, tg = lane & 3;
    #pragma unroll
    for (int i = 0; i < 2; i++){
        const int rloc = bm*128 + warpM*32 + i*16 + gi;
        const float inv0 = 1.f / rowsum[(size_t)z * Sz + rloc];
        const float inv1 = 1.f / rowsum[(size_t)z * Sz + rloc + 8];
        const size_t row0 = (size_t)(b*Sz) + rloc;
        #pragma unroll
        for (int j = 0; j < 8; j++){
            const int col = h*DHz + warpN*64 + j*8 + tg*2;
            float2 v0 = make_float2(tf32r(acc[i][j][0]*inv0), tf32r(acc[i][j][1]*inv0));
            float2 v1 = make_float2(tf32r(acc[i][j][2]*inv1), tf32r(acc[i][j][3]*inv1));
            *(float2*)&Cx[row0 * Dz + col]     = v0;
            *(float2*)&Cx[(row0+8) * Dz + col] = v1;
        }
    }
}

// ================= helpers / elementwise =================
__global__ __launch_bounds__(256) void tf32_round_kernel(
    const float* __restrict__ src, float* __restrict__ dst, int n4)
{
    const int i = blockIdx.x * 256 + threadIdx.x;
    if (i >= n4) return;
    float4 v = *(const float4*)(src + (size_t)i*4);
    v.x = tf32r(v.x); v.y = tf32r(v.y); v.z = tf32r(v.z); v.w = tf32r(v.w);
    *(float4*)(dst + (size_t)i*4) = v;
}

// transpose v[token][Dz] -> vt[(b*16+h)*128+dh][token_in_batch], rounded
__global__ __launch_bounds__(256) void transpose_v(const float* __restrict__ v, float* __restrict__ vt)
{
    __shared__ float tile[32][33];
    const int tid = threadIdx.x;
    const int d0 = blockIdx.x * 32, t0 = blockIdx.y * 32;
    const int tx = tid & 31, ty = tid >> 5;
    #pragma unroll
    for (int it = 0; it < 4; it++){
        const int tok = t0 + ty + it*8;
        tile[ty + it*8][tx] = v[(size_t)tok * Dz + d0 + tx];
    }
    __syncthreads();
    #pragma unroll
    for (int it = 0; it < 4; it++){
        const int dh_loc = ty + it*8;
        const int gd = d0 + dh_loc;
        const int tok = t0 + tx;
        const int bb = tok >> 11, tin = tok & 2047;
        vt[((size_t)(bb*16) * 128 + gd) * Sz + tin] = tf32r(tile[tx][dh_loc]);
    }
}

__global__ __launch_bounds__(256) void rmsnorm_kernel(
    const float* __restrict__ x, const float* __restrict__ w,
    float* __restrict__ out, float* __restrict__ out_raw)
{
    const int row = blockIdx.x;
    const float* xr = x + (size_t)row * Dz;
    float* orow = out + (size_t)row * Dz;
    const int tid = threadIdx.x;
    float ss = 0.f;
    #pragma unroll
    for (int i = tid*4; i < Dz; i += 1024) {
        float4 v = *(const float4*)(xr + i);
        ss += v.x*v.x + v.y*v.y + v.z*v.z + v.w*v.w;
    }
    __shared__ float red[256];
    red[tid] = ss; __syncthreads();
    for (int s = 128; s > 0; s >>= 1) { if (tid < s) red[tid] += red[tid+s]; __syncthreads(); }
    const float scale = rsqrtf(red[0] / (float)Dz + 1e-6f);
    #pragma unroll
    for (int i = tid*4; i < Dz; i += 1024) {
        float4 v = *(const float4*)(xr + i);
        float4 ww = *(const float4*)(w + i);
        float4 o;
        o.x = v.x*scale*ww.x; o.y = v.y*scale*ww.y;
        o.z = v.z*scale*ww.z; o.w = v.w*scale*ww.w;
        if (out_raw) *(float4*)(out_raw + (size_t)row * Dz + i) = o;
        o.x = tf32r(o.x); o.y = tf32r(o.y); o.z = tf32r(o.z); o.w = tf32r(o.w);
        *(float4*)(orow + i) = o;
    }
}

__global__ __launch_bounds__(256) void rope_kernel(float* __restrict__ q, float* __restrict__ k)
{
    const size_t idx = (size_t)blockIdx.x * 256 + threadIdx.x;
    if (idx >= (size_t)NTz * Hz * 64) return;
    const int    j    = (int)(idx & 63);
    const size_t th   = idx >> 6;
    const int    head = (int)(th & 15);
    const size_t tok  = th >> 4;
    const int    s    = (int)(tok & (Sz - 1));
    const double inv  = exp(-(double)(2*j) / 128.0 * 9.210340371976184);
    const double ang  = (double)s * inv;
    const float  c  = (float)cos(ang);
    const float  sn = (float)sin(ang);
    const size_t base = tok * (size_t)Dz + (size_t)head * DHz + j;
    float q1 = q[base], q2 = q[base + 64];
    q[base]      = tf32r(q1*c - q2*sn);
    q[base + 64] = tf32r(q2*c + q1*sn);
    float k1 = k[base], k2 = k[base + 64];
    k[base]      = tf32r(k1*c - k2*sn);
    k[base + 64] = tf32r(k2*c + k1*sn);
}

__global__ __launch_bounds__(256) void softmax_kernel(float* __restrict__ Sc, float* __restrict__ rowsum)
{
    const size_t row = blockIdx.x;
    float* p = Sc + row * (size_t)Sz;
    const int tid = threadIdx.x;
    float m = -1e30f;
    #pragma unroll
    for (int i = tid*4; i < Sz; i += 1024) {
        float4 v = *(const float4*)(p + i);
        m = fmaxf(m, fmaxf(fmaxf(v.x, v.y), fmaxf(v.z, v.w)));
    }
    __shared__ float red[256];
    red[tid] = m; __syncthreads();
    for (int s = 128; s > 0; s >>= 1) { if (tid < s) red[tid] = fmaxf(red[tid], red[tid+s]); __syncthreads(); }
    m = red[0];
    __syncthreads();
    float sum = 0.f;
    #pragma unroll
    for (int i = tid*4; i < Sz; i += 1024) {
        float4 v = *(const float4*)(p + i);
        v.x = tf32r(expf(v.x - m)); v.y = tf32r(expf(v.y - m));
        v.z = tf32r(expf(v.z - m)); v.w = tf32r(expf(v.w - m));
        sum += v.x + v.y + v.z + v.w;
        *(float4*)(p + i) = v;
    }
    red[tid] = sum; __syncthreads();
    for (int s = 128; s > 0; s >>= 1) { if (tid < s) red[tid] += red[tid+s]; __syncthreads(); }
    if (tid == 0) rowsum[row] = red[0];
}

__global__ __launch_bounds__(256) void router_kernel(
    const float* __restrict__ h, const float* __restrict__ rw,
    const float* __restrict__ rb, int* __restrict__ choice)
{
    const int t = blockIdx.x;
    const float* xr = h + (size_t)t * Dz;
    const int tid = threadIdx.x;
    float s0 = 0.f, s1 = 0.f;
    #pragma unroll
    for (int i = tid*4; i < Dz; i += 1024) {
        float4 v  = *(const float4*)(xr + i);
        float4 w0 = *(const float4*)(rw + i);
        float4 w1 = *(const float4*)(rw + Dz + i);
        s0 += v.x*w0.x + v.y*w0.y + v.z*w0.z + v.w*w0.w;
        s1 += v.x*w1.x + v.y*w1.y + v.z*w1.z + v.w*w1.w;
    }
    __shared__ float r0[256], r1[256];
    r0[tid] = s0; r1[tid] = s1; __syncthreads();
    for (int s = 128; s > 0; s >>= 1) {
        if (tid < s) { r0[tid] += r0[tid+s]; r1[tid] += r1[tid+s]; }
        __syncthreads();
    }
    if (tid == 0) {
        const float l0 = r0[0] + rb[0], l1 = r1[0] + rb[1];
        choice[t] = (l1 > l0) ? 1 : 0;
    }
}

__global__ __launch_bounds__(256) void act_kernel(
    float* __restrict__ gate, const float* __restrict__ up,
    const int* __restrict__ choice, int e)
{
    const int f = blockIdx.x * 256 + threadIdx.x;
    if (f >= Fz) return;
    const int tok = blockIdx.y;
    const size_t idx = (size_t)tok * Fz + f;
    if (choice[tok] == e) {
        const float g = gate[idx];
        gate[idx] = tf32r((g / (1.f + expf(-g))) * up[idx]);
    } else {
        gate[idx] = 0.f;
    }
}

// ================= launch =================
extern "C" void kernel_launch(void* const* d_in, const int* in_sizes, int n_in,
                              void* d_out, int out_size)
{
    const float* x    = (const float*)d_in[0];
    const float* ln1w = (const float*)d_in[1];
    const float* wq   = (const float*)d_in[2];
    const float* bq   = (const float*)d_in[3];
    const float* wk   = (const float*)d_in[4];
    const float* bk   = (const float*)d_in[5];
    const float* wv   = (const float*)d_in[6];
    const float* bv   = (const float*)d_in[7];
    const float* wo   = (const float*)d_in[8];
    const float* ln2w = (const float*)d_in[9];
    const float* e1g  = (const float*)d_in[10];
    const float* e1u  = (const float*)d_in[11];
    const float* e1d  = (const float*)d_in[12];
    const float* e2g  = (const float*)d_in[13];
    const float* e2u  = (const float*)d_in[14];
    const float* e2d  = (const float*)d_in[15];
    const float* rw   = (const float*)d_in[16];
    const float* rb   = (const float*)d_in[17];
    float* out = (float*)d_out;

    float *h1, *q, *k, *v, *ctx, *h2, *sc, *rs, *gate, *up, *wr;
    int* choice;
    cudaGetSymbolAddress((void**)&h1,  g_h1);
    cudaGetSymbolAddress((void**)&q,   g_q);
    cudaGetSymbolAddress((void**)&k,   g_k);
    cudaGetSymbolAddress((void**)&v,   g_v);
    cudaGetSymbolAddress((void**)&ctx, g_ctx);
    cudaGetSymbolAddress((void**)&h2,  g_h2);
    cudaGetSymbolAddress((void**)&sc,  g_sc);
    cudaGetSymbolAddress((void**)&rs,  g_rs);
    cudaGetSymbolAddress((void**)&gate, g_gate);
    cudaGetSymbolAddress((void**)&up,   g_up);
    cudaGetSymbolAddress((void**)&wr,   g_wr);
    cudaGetSymbolAddress((void**)&choice, g_choice);

    const int SMEM_NT = STAGE_NT * 2 * 4;   // 73728 B
    cudaFuncSetAttribute(tf32_gemm_nt, cudaFuncAttributeMaxDynamicSharedMemorySize, SMEM_NT);
    cudaFuncSetAttribute(tf32_scores,  cudaFuncAttributeMaxDynamicSharedMemorySize, SMEM_NT);
    cudaFuncSetAttribute(tf32_ctx,     cudaFuncAttributeMaxDynamicSharedMemorySize, SMEM_NT);

    // --- weight pre-rounding (TF32) ---
    #define RND(src, off, n) tf32_round_kernel<<<((n)/4+255)/256, 256>>>(src, wr + (size_t)(off), (n)/4)
    RND(wq,  WR_Q,   Dz*Dz);  RND(wk,  WR_K,   Dz*Dz);
    RND(wv,  WR_V,   Dz*Dz);  RND(wo,  WR_O,   Dz*Dz);
    RND(e1g, WR_E1G, Fz*Dz);  RND(e1u, WR_E1U, Fz*Dz);  RND(e1d, WR_E1D, Fz*Dz);
    RND(e2g, WR_E2G, Fz*Dz);  RND(e2u, WR_E2U, Fz*Dz);  RND(e2d, WR_E2D, Fz*Dz);
    #undef RND

    // --- attention block ---
    rmsnorm_kernel<<<NTz, 256>>>(x, ln1w, h1, nullptr);
    tf32_gemm_nt<<<dim3(Dz/128, NTz/128), 256, SMEM_NT>>>(h1, wr+WR_Q, q, bq, nullptr, NTz, Dz, Dz);
    tf32_gemm_nt<<<dim3(Dz/128, NTz/128), 256, SMEM_NT>>>(h1, wr+WR_K, k, bk, nullptr, NTz, Dz, Dz);
    tf32_gemm_nt<<<dim3(Dz/128, NTz/128), 256, SMEM_NT>>>(h1, wr+WR_V, v, bv, nullptr, NTz, Dz, Dz);
    rope_kernel<<<(NTz*Hz*64)/256, 256>>>(q, k);
    tf32_scores<<<dim3(Sz/128, Sz/128, BHz), 256, SMEM_NT>>>(q, k, sc);
    // after scores has consumed k, reuse its memory as vt
    float* vt = k;
    transpose_v<<<dim3(Dz/32, NTz/32), 256>>>(v, vt);
    softmax_kernel<<<BHz*Sz, 256>>>(sc, rs);
    tf32_ctx<<<dim3(1, Sz/128, BHz), 256, SMEM_NT>>>(sc, vt, rs, ctx);
    tf32_gemm_nt<<<dim3(Dz/128, NTz/128), 256, SMEM_NT>>>(ctx, wr+WR_O, h2, nullptr, x, NTz, Dz, Dz);

    // --- MoE block --- (q buffer reused as fp32 h3 for the router)
    rmsnorm_kernel<<<NTz, 256>>>(h2, ln2w, h1, q);
    router_kernel<<<NTz, 256>>>(q, rw, rb, choice);

    tf32_gemm_nt<<<dim3(Fz/128, NTz/128), 256, SMEM_NT>>>(h1, wr+WR_E1G, gate, nullptr, nullptr, NTz, Fz, Dz);
    tf32_gemm_nt<<<dim3(Fz/128, NTz/128), 256, SMEM_NT>>>(h1, wr+WR_E1U, up,   nullptr, nullptr, NTz, Fz, Dz);
    act_kernel<<<dim3((Fz+255)/256, NTz), 256>>>(gate, up, choice, 0);
    tf32_gemm_nt<<<dim3(Dz/128, NTz/128), 256, SMEM_NT>>>(gate, wr+WR_E1D, out, nullptr, h2, NTz, Dz, Fz);

    tf32_gemm_nt<<<dim3(Fz/128, NTz/128), 256, SMEM_NT>>>(h1, wr+WR_E2G, gate, nullptr, nullptr, NTz, Fz, Dz);
    tf32_gemm_nt<<<dim3(Fz/128, NTz/128), 256, SMEM_NT>>>(h1, wr+WR_E2U, up,   nullptr, nullptr, NTz, Fz, Dz);
    act_kernel<<<dim3((Fz+255)/256, NTz), 256>>>(gate, up, choice, 1);
    tf32_gemm_nt<<<dim3(Dz/128, NTz/128), 256, SMEM_NT>>>(gate, wr+WR_E2D, out, nullptr, out, NTz, Dz, Fz);
}

// round 10
// speedup vs baseline: 1.1578x; 1.0434x over previous
#include <cuda_runtime.h>
#include <math.h>
#include <stdint.h>

#define Bz   2
#define Sz   2048
#define Dz   2048
#define Hz   16
#define DHz  128
#define Fz   5504
#define NTz  (Bz*Sz)      // 4096 tokens
#define BHz  (Bz*Hz)      // 32
#define ATTN_SCALE 0.08838834764831845f   // 1/sqrt(128)

// ---------------- scratch (device globals; allocation-free) ----------------
__device__ float g_h1 [(size_t)NTz*Dz];      // rounded rmsnorm out
__device__ float g_q  [(size_t)NTz*Dz];      // q; later fp32 h3 for router
__device__ float g_k  [(size_t)NTz*Dz];      // k; later vt (transposed V)
__device__ float g_v  [(size_t)NTz*Dz];
__device__ float g_ctx[(size_t)NTz*Dz];
__device__ float g_h2 [(size_t)NTz*Dz];
__device__ float g_sc [(size_t)BHz*Sz*Sz];   // 512 MB scores/probs
__device__ float g_rs [(size_t)BHz*Sz];
__device__ float g_gate[(size_t)NTz*Fz];
__device__ float g_up  [(size_t)NTz*Fz];
__device__ int   g_choice[NTz];
// pre-rounded (TF32) weights
#define WR_Q   0
#define WR_K   4194304
#define WR_V   8388608
#define WR_O   12582912
#define WR_E1G 16777216
#define WR_E1U 28049408
#define WR_E1D 39321600
#define WR_E2G 50593792
#define WR_E2U 61865984
#define WR_E2D 73138176
#define WR_TOT 84410368
__device__ float g_wr[(size_t)WR_TOT];

// ================= TF32 MMA machinery =================
// Block tile 128x128x32, 256 threads, warp tile 32(M)x64(N).
// Operands in smem [row][k] pitch 36, pre-rounded to TF32 -> inner loop is
// pure LDS.128 + MMA. 3-stage cp.async ring, ONE __syncthreads per K-iter.

#define PITCH  36
#define A_FLOATS (128*PITCH)           // 4608
#define STAGE_NT (2*A_FLOATS)          // 9216 floats = 36864 B
#define NSTAGE 3
#define SMEM_BYTES (NSTAGE*STAGE_NT*4) // 110592 B

__device__ __forceinline__ unsigned sptr(const void* p){ return (unsigned)__cvta_generic_to_shared(p); }
__device__ __forceinline__ void cpa16(unsigned s, const float* g){
    asm volatile("cp.async.cg.shared.global [%0], [%1], 16;\n" :: "r"(s), "l"(g));
}
__device__ __forceinline__ void cpcommit(){ asm volatile("cp.async.commit_group;\n" ::); }
__device__ __forceinline__ void cpwait1(){ asm volatile("cp.async.wait_group 1;\n" ::); }
__device__ __forceinline__ float tf32r(float f){
    unsigned u; asm("cvt.rna.tf32.f32 %0, %1;" : "=r"(u) : "f"(f)); return __uint_as_float(u);
}
__device__ __forceinline__ void mma8(float* c, unsigned a0,unsigned a1,unsigned a2,unsigned a3,
                                     unsigned b0, unsigned b1){
    asm volatile("mma.sync.aligned.m16n8k8.row.col.f32.tf32.tf32.f32 "
                 "{%0,%1,%2,%3},{%4,%5,%6,%7},{%8,%9},{%0,%1,%2,%3};\n"
                 : "+f"(c[0]),"+f"(c[1]),"+f"(c[2]),"+f"(c[3])
                 : "r"(a0),"r"(a1),"r"(a2),"r"(a3),"r"(b0),"r"(b1));
}

// load 128 rows x 32 k-cols into smem [row][k] pitch 36
__device__ __forceinline__ void load_tile_rowk(float* S, const float* G, int ld, int tid){
    const int r = tid >> 1, cb = (tid & 1) * 4;
    const float* g = G + (size_t)r * ld + cb;
    unsigned s = sptr(S) + (unsigned)(r * PITCH + cb) * 4u;
    #pragma unroll
    for (int it = 0; it < 4; it++) cpa16(s + it * 32u, g + it * 8);
}

// Virtual-K bijection: MMA chunk (half, c), thread tg supplies physical
// k0 = tg*8 + half*4 + 2c, k1 = k0 + 1 (identical on A and B -> exact).
__device__ __forceinline__ void compute_nt(const float* __restrict__ Asf, const float* __restrict__ Bsf,
                                           float acc[2][8][4], int warpM, int warpN, int lane){
    const unsigned* As = (const unsigned*)Asf;
    const unsigned* Bs = (const unsigned*)Bsf;
    const int gi = lane >> 2, tg = lane & 3;
    const int r0 = warpM*32 + gi;
    #pragma unroll
    for (int half = 0; half < 2; half++){
        unsigned a[4][4];
        #pragma unroll
        for (int r = 0; r < 4; r++)
            *(uint4*)a[r] = *(const uint4*)(As + (r0 + r*8)*PITCH + tg*8 + half*4);
        #pragma unroll
        for (int j = 0; j < 8; j++){
            const int n = warpN*64 + j*8 + gi;
            unsigned b[4];
            *(uint4*)b = *(const uint4*)(Bs + n*PITCH + tg*8 + half*4);
            #pragma unroll
            for (int c = 0; c < 2; c++){
                mma8(acc[0][j], a[0][2*c], a[1][2*c], a[0][2*c+1], a[1][2*c+1], b[2*c], b[2*c+1]);
                mma8(acc[1][j], a[2][2*c], a[3][2*c], a[2][2*c+1], a[3][2*c+1], b[2*c], b[2*c+1]);
            }
        }
    }
}

// 3-stage ring mainloop: compute buf t%3, prefetch buf (t+2)%3, one sync/iter.
__device__ __forceinline__ void mainloop(float* sm, const float* Ag, int lda,
                                         const float* Bg, int ldb, int T,
                                         float acc[2][8][4], int warpM, int warpN, int lane, int tid){
    load_tile_rowk(sm, Ag, lda, tid);
    load_tile_rowk(sm + A_FLOATS, Bg, ldb, tid);
    cpcommit();
    load_tile_rowk(sm + STAGE_NT, Ag + 32, lda, tid);
    load_tile_rowk(sm + STAGE_NT + A_FLOATS, Bg + 32, ldb, tid);
    cpcommit();
    for (int t = 0; t < T; t++){
        cpwait1();
        __syncthreads();
        const int u = t + 2;
        if (u < T){
            float* Sd = sm + (u % NSTAGE) * STAGE_NT;
            load_tile_rowk(Sd, Ag + u*32, lda, tid);
            load_tile_rowk(Sd + A_FLOATS, Bg + u*32, ldb, tid);
        }
        cpcommit();   // every iter (possibly empty) keeps wait_group semantics exact
        const float* Sa = sm + (t % NSTAGE) * STAGE_NT;
        compute_nt(Sa, Sa + A_FLOATS, acc, warpM, warpN, lane);
    }
}

#define ACC_INIT() float acc[2][8][4]; \
    _Pragma("unroll") for (int i=0;i<2;i++) \
    _Pragma("unroll") for (int j=0;j<8;j++) \
    _Pragma("unroll") for (int c=0;c<4;c++) acc[i][j][c]=0.f;

// ---------- generic NT: C[M,N] = A[M,K] * B[N,K]^T (+bias)(+add), A/B pre-TF32 ----------
extern __shared__ float smem[];
__global__ __launch_bounds__(256, 2) void tf32_gemm_nt(
    const float* __restrict__ A, const float* __restrict__ B,
    float* __restrict__ C, const float* __restrict__ bias,
    const float* __restrict__ add, int M, int N, int K)
{
    const int tid = threadIdx.x, lane = tid & 31, warp = tid >> 5;
    const int warpM = warp & 3, warpN = warp >> 2;
    const int bm = blockIdx.y, bn = blockIdx.x;
    ACC_INIT();
    mainloop(smem, A + (size_t)bm*128*K, K, B + (size_t)bn*128*K, K, K/32,
             acc, warpM, warpN, lane, tid);
    const int gi = lane >> 2, tg = lane & 3;
    #pragma unroll
    for (int i = 0; i < 2; i++){
        const int row = bm*128 + warpM*32 + i*16 + gi;
        #pragma unroll
        for (int j = 0; j < 8; j++){
            const int col = bn*128 + warpN*64 + j*8 + tg*2;
            float2 v0 = make_float2(acc[i][j][0], acc[i][j][1]);
            float2 v1 = make_float2(acc[i][j][2], acc[i][j][3]);
            if (bias){
                const float b0 = bias[col], b1 = bias[col+1];
                v0.x += b0; v0.y += b1; v1.x += b0; v1.y += b1;
            }
            if (add){
                float2 r0 = *(const float2*)&add[(size_t)row * N + col];
                float2 r1 = *(const float2*)&add[(size_t)(row+8) * N + col];
                v0.x += r0.x; v0.y += r0.y; v1.x += r1.x; v1.y += r1.y;
            }
            *(float2*)&C[(size_t)row * N + col]     = v0;
            *(float2*)&C[(size_t)(row+8) * N + col] = v1;
        }
    }
}

// ---------- attention scores: causal, scaled; masked blocks SKIPPED ----------
__global__ __launch_bounds__(256, 2) void tf32_scores(
    const float* __restrict__ Q, const float* __restrict__ Km, float* __restrict__ Sc)
{
    const int bm = blockIdx.y, bn = blockIdx.x;
    if (bn > bm) return;   // never read downstream (softmax/ctx are causal-trimmed)
    const int z = blockIdx.z, b = z >> 4, h = z & 15;
    const int tid = threadIdx.x, lane = tid & 31, warp = tid >> 5;
    const int warpM = warp & 3, warpN = warp >> 2;
    float* Cb = Sc + (size_t)z * Sz * Sz;
    const float* Ag = Q  + (size_t)(b*Sz + bm*128) * Dz + (size_t)h * DHz;
    const float* Bg = Km + (size_t)(b*Sz + bn*128) * Dz + (size_t)h * DHz;
    ACC_INIT();
    mainloop(smem, Ag, Dz, Bg, Dz, DHz/32, acc, warpM, warpN, lane, tid);
    const int gi = lane >> 2, tg = lane & 3;
    #pragma unroll
    for (int i = 0; i < 2; i++){
        const int row0 = bm*128 + warpM*32 + i*16 + gi;
        #pragma unroll
        for (int j = 0; j < 8; j++){
            const int col = bn*128 + warpN*64 + j*8 + tg*2;
            float2 v0, v1;
            v0.x = (col   <= row0  ) ? acc[i][j][0]*ATTN_SCALE : -1e30f;
            v0.y = (col+1 <= row0  ) ? acc[i][j][1]*ATTN_SCALE : -1e30f;
            v1.x = (col   <= row0+8) ? acc[i][j][2]*ATTN_SCALE : -1e30f;
            v1.y = (col+1 <= row0+8) ? acc[i][j][3]*ATTN_SCALE : -1e30f;
            *(float2*)&Cb[(size_t)row0 * Sz + col]     = v0;
            *(float2*)&Cb[(size_t)(row0+8) * Sz + col] = v1;
        }
    }
}

// ---------- attention ctx: Cx = P Vt^T, causal K-trim, normalized, rounded ----------
__global__ __launch_bounds__(256, 2) void tf32_ctx(
    const float* __restrict__ P, const float* __restrict__ Vt,
    const float* __restrict__ rowsum, float* __restrict__ Cx)
{
    const int z = blockIdx.z, b = z >> 4, h = z & 15;
    const int bm = blockIdx.y;
    const int tid = threadIdx.x, lane = tid & 31, warp = tid >> 5;
    const int warpM = warp & 3, warpN = warp >> 2;
    const float* Ag = P  + (size_t)z * Sz * Sz + (size_t)bm * 128 * Sz;
    const float* Bg = Vt + (size_t)z * 128 * Sz;
    ACC_INIT();
    mainloop(smem, Ag, Sz, Bg, Sz, (bm + 1) * 4, acc, warpM, warpN, lane, tid);
    const int gi = lane >> 2, tg = lane & 3;
    #pragma unroll
    for (int i = 0; i < 2; i++){
        const int rloc = bm*128 + warpM*32 + i*16 + gi;
        const float inv0 = 1.f / rowsum[(size_t)z * Sz + rloc];
        const float inv1 = 1.f / rowsum[(size_t)z * Sz + rloc + 8];
        const size_t row0 = (size_t)(b*Sz) + rloc;
        #pragma unroll
        for (int j = 0; j < 8; j++){
            const int col = h*DHz + warpN*64 + j*8 + tg*2;
            float2 v0 = make_float2(tf32r(acc[i][j][0]*inv0), tf32r(acc[i][j][1]*inv0));
            float2 v1 = make_float2(tf32r(acc[i][j][2]*inv1), tf32r(acc[i][j][3]*inv1));
            *(float2*)&Cx[row0 * Dz + col]     = v0;
            *(float2*)&Cx[(row0+8) * Dz + col] = v1;
        }
    }
}

// ================= helpers / elementwise =================
__global__ __launch_bounds__(256) void tf32_round_kernel(
    const float* __restrict__ src, float* __restrict__ dst, int n4)
{
    const int i = blockIdx.x * 256 + threadIdx.x;
    if (i >= n4) return;
    float4 v = *(const float4*)(src + (size_t)i*4);
    v.x = tf32r(v.x); v.y = tf32r(v.y); v.z = tf32r(v.z); v.w = tf32r(v.w);
    *(float4*)(dst + (size_t)i*4) = v;
}

// transpose v[token][Dz] -> vt[(b*16+h)*128+dh][token_in_batch], rounded
__global__ __launch_bounds__(256) void transpose_v(const float* __restrict__ v, float* __restrict__ vt)
{
    __shared__ float tile[32][33];
    const int tid = threadIdx.x;
    const int d0 = blockIdx.x * 32, t0 = blockIdx.y * 32;
    const int tx = tid & 31, ty = tid >> 5;
    #pragma unroll
    for (int it = 0; it < 4; it++){
        const int tok = t0 + ty + it*8;
        tile[ty + it*8][tx] = v[(size_t)tok * Dz + d0 + tx];
    }
    __syncthreads();
    #pragma unroll
    for (int it = 0; it < 4; it++){
        const int dh_loc = ty + it*8;
        const int gd = d0 + dh_loc;
        const int tok = t0 + tx;
        const int bb = tok >> 11, tin = tok & 2047;
        vt[((size_t)(bb*16) * 128 + gd) * Sz + tin] = tf32r(tile[tx][dh_loc]);
    }
}

__global__ __launch_bounds__(256) void rmsnorm_kernel(
    const float* __restrict__ x, const float* __restrict__ w,
    float* __restrict__ out, float* __restrict__ out_raw)
{
    const int row = blockIdx.x;
    const float* xr = x + (size_t)row * Dz;
    float* orow = out + (size_t)row * Dz;
    const int tid = threadIdx.x;
    float ss = 0.f;
    #pragma unroll
    for (int i = tid*4; i < Dz; i += 1024) {
        float4 v = *(const float4*)(xr + i);
        ss += v.x*v.x + v.y*v.y + v.z*v.z + v.w*v.w;
    }
    __shared__ float red[256];
    red[tid] = ss; __syncthreads();
    for (int s = 128; s > 0; s >>= 1) { if (tid < s) red[tid] += red[tid+s]; __syncthreads(); }
    const float scale = rsqrtf(red[0] / (float)Dz + 1e-6f);
    #pragma unroll
    for (int i = tid*4; i < Dz; i += 1024) {
        float4 v = *(const float4*)(xr + i);
        float4 ww = *(const float4*)(w + i);
        float4 o;
        o.x = v.x*scale*ww.x; o.y = v.y*scale*ww.y;
        o.z = v.z*scale*ww.z; o.w = v.w*scale*ww.w;
        if (out_raw) *(float4*)(out_raw + (size_t)row * Dz + i) = o;
        o.x = tf32r(o.x); o.y = tf32r(o.y); o.z = tf32r(o.z); o.w = tf32r(o.w);
        *(float4*)(orow + i) = o;
    }
}

__global__ __launch_bounds__(256) void rope_kernel(float* __restrict__ q, float* __restrict__ k)
{
    const size_t idx = (size_t)blockIdx.x * 256 + threadIdx.x;
    if (idx >= (size_t)NTz * Hz * 64) return;
    const int    j    = (int)(idx & 63);
    const size_t th   = idx >> 6;
    const int    head = (int)(th & 15);
    const size_t tok  = th >> 4;
    const int    s    = (int)(tok & (Sz - 1));
    const double inv  = exp(-(double)(2*j) / 128.0 * 9.210340371976184);
    const double ang  = (double)s * inv;
    const float  c  = (float)cos(ang);
    const float  sn = (float)sin(ang);
    const size_t base = tok * (size_t)Dz + (size_t)head * DHz + j;
    float q1 = q[base], q2 = q[base + 64];
    q[base]      = tf32r(q1*c - q2*sn);
    q[base + 64] = tf32r(q2*c + q1*sn);
    float k1 = k[base], k2 = k[base + 64];
    k[base]      = tf32r(k1*c - k2*sn);
    k[base + 64] = tf32r(k2*c + k1*sn);
}

// causal softmax: only the first ((row_blk)+1)*128 columns are live
__global__ __launch_bounds__(256) void softmax_kernel(float* __restrict__ Sc, float* __restrict__ rowsum)
{
    const size_t row = blockIdx.x;
    const int sloc = (int)(row & (Sz - 1));
    const int len = ((sloc >> 7) + 1) << 7;
    float* p = Sc + row * (size_t)Sz;
    const int tid = threadIdx.x;
    float m = -1e30f;
    for (int i = tid*4; i < len; i += 1024) {
        float4 v = *(const float4*)(p + i);
        m = fmaxf(m, fmaxf(fmaxf(v.x, v.y), fmaxf(v.z, v.w)));
    }
    __shared__ float red[256];
    red[tid] = m; __syncthreads();
    for (int s = 128; s > 0; s >>= 1) { if (tid < s) red[tid] = fmaxf(red[tid], red[tid+s]); __syncthreads(); }
    m = red[0];
    __syncthreads();
    float sum = 0.f;
    for (int i = tid*4; i < len; i += 1024) {
        float4 v = *(const float4*)(p + i);
        v.x = tf32r(expf(v.x - m)); v.y = tf32r(expf(v.y - m));
        v.z = tf32r(expf(v.z - m)); v.w = tf32r(expf(v.w - m));
        sum += v.x + v.y + v.z + v.w;
        *(float4*)(p + i) = v;
    }
    red[tid] = sum; __syncthreads();
    for (int s = 128; s > 0; s >>= 1) { if (tid < s) red[tid] += red[tid+s]; __syncthreads(); }
    if (tid == 0) rowsum[row] = red[0];
}

__global__ __launch_bounds__(256) void router_kernel(
    const float* __restrict__ h, const float* __restrict__ rw,
    const float* __restrict__ rb, int* __restrict__ choice)
{
    const int t = blockIdx.x;
    const float* xr = h + (size_t)t * Dz;
    const int tid = threadIdx.x;
    float s0 = 0.f, s1 = 0.f;
    #pragma unroll
    for (int i = tid*4; i < Dz; i += 1024) {
        float4 v  = *(const float4*)(xr + i);
        float4 w0 = *(const float4*)(rw + i);
        float4 w1 = *(const float4*)(rw + Dz + i);
        s0 += v.x*w0.x + v.y*w0.y + v.z*w0.z + v.w*w0.w;
        s1 += v.x*w1.x + v.y*w1.y + v.z*w1.z + v.w*w1.w;
    }
    __shared__ float r0[256], r1[256];
    r0[tid] = s0; r1[tid] = s1; __syncthreads();
    for (int s = 128; s > 0; s >>= 1) {
        if (tid < s) { r0[tid] += r0[tid+s]; r1[tid] += r1[tid+s]; }
        __syncthreads();
    }
    if (tid == 0) {
        const float l0 = r0[0] + rb[0], l1 = r1[0] + rb[1];
        choice[t] = (l1 > l0) ? 1 : 0;
    }
}

__global__ __launch_bounds__(256) void act_kernel(
    float* __restrict__ gate, const float* __restrict__ up,
    const int* __restrict__ choice, int e)
{
    const int f = blockIdx.x * 256 + threadIdx.x;
    if (f >= Fz) return;
    const int tok = blockIdx.y;
    const size_t idx = (size_t)tok * Fz + f;
    if (choice[tok] == e) {
        const float g = gate[idx];
        gate[idx] = tf32r((g / (1.f + expf(-g))) * up[idx]);
    } else {
        gate[idx] = 0.f;
    }
}

// ================= launch =================
extern "C" void kernel_launch(void* const* d_in, const int* in_sizes, int n_in,
                              void* d_out, int out_size)
{
    const float* x    = (const float*)d_in[0];
    const float* ln1w = (const float*)d_in[1];
    const float* wq   = (const float*)d_in[2];
    const float* bq   = (const float*)d_in[3];
    const float* wk   = (const float*)d_in[4];
    const float* bk   = (const float*)d_in[5];
    const float* wv   = (const float*)d_in[6];
    const float* bv   = (const float*)d_in[7];
    const float* wo   = (const float*)d_in[8];
    const float* ln2w = (const float*)d_in[9];
    const float* e1g  = (const float*)d_in[10];
    const float* e1u  = (const float*)d_in[11];
    const float* e1d  = (const float*)d_in[12];
    const float* e2g  = (const float*)d_in[13];
    const float* e2u  = (const float*)d_in[14];
    const float* e2d  = (const float*)d_in[15];
    const float* rw   = (const float*)d_in[16];
    const float* rb   = (const float*)d_in[17];
    float* out = (float*)d_out;

    float *h1, *q, *k, *v, *ctx, *h2, *sc, *rs, *gate, *up, *wr;
    int* choice;
    cudaGetSymbolAddress((void**)&h1,  g_h1);
    cudaGetSymbolAddress((void**)&q,   g_q);
    cudaGetSymbolAddress((void**)&k,   g_k);
    cudaGetSymbolAddress((void**)&v,   g_v);
    cudaGetSymbolAddress((void**)&ctx, g_ctx);
    cudaGetSymbolAddress((void**)&h2,  g_h2);
    cudaGetSymbolAddress((void**)&sc,  g_sc);
    cudaGetSymbolAddress((void**)&rs,  g_rs);
    cudaGetSymbolAddress((void**)&gate, g_gate);
    cudaGetSymbolAddress((void**)&up,   g_up);
    cudaGetSymbolAddress((void**)&wr,   g_wr);
    cudaGetSymbolAddress((void**)&choice, g_choice);

    cudaFuncSetAttribute(tf32_gemm_nt, cudaFuncAttributeMaxDynamicSharedMemorySize, SMEM_BYTES);
    cudaFuncSetAttribute(tf32_scores,  cudaFuncAttributeMaxDynamicSharedMemorySize, SMEM_BYTES);
    cudaFuncSetAttribute(tf32_ctx,     cudaFuncAttributeMaxDynamicSharedMemorySize, SMEM_BYTES);

    // --- weight pre-rounding (TF32) ---
    #define RND(src, off, n) tf32_round_kernel<<<((n)/4+255)/256, 256>>>(src, wr + (size_t)(off), (n)/4)
    RND(wq,  WR_Q,   Dz*Dz);  RND(wk,  WR_K,   Dz*Dz);
    RND(wv,  WR_V,   Dz*Dz);  RND(wo,  WR_O,   Dz*Dz);
    RND(e1g, WR_E1G, Fz*Dz);  RND(e1u, WR_E1U, Fz*Dz);  RND(e1d, WR_E1D, Fz*Dz);
    RND(e2g, WR_E2G, Fz*Dz);  RND(e2u, WR_E2U, Fz*Dz);  RND(e2d, WR_E2D, Fz*Dz);
    #undef RND

    // --- attention block ---
    rmsnorm_kernel<<<NTz, 256>>>(x, ln1w, h1, nullptr);
    tf32_gemm_nt<<<dim3(Dz/128, NTz/128), 256, SMEM_BYTES>>>(h1, wr+WR_Q, q, bq, nullptr, NTz, Dz, Dz);
    tf32_gemm_nt<<<dim3(Dz/128, NTz/128), 256, SMEM_BYTES>>>(h1, wr+WR_K, k, bk, nullptr, NTz, Dz, Dz);
    tf32_gemm_nt<<<dim3(Dz/128, NTz/128), 256, SMEM_BYTES>>>(h1, wr+WR_V, v, bv, nullptr, NTz, Dz, Dz);
    rope_kernel<<<(NTz*Hz*64)/256, 256>>>(q, k);
    tf32_scores<<<dim3(Sz/128, Sz/128, BHz), 256, SMEM_BYTES>>>(q, k, sc);
    float* vt = k;   // k's memory reused as transposed V after scores consumed it
    transpose_v<<<dim3(Dz/32, NTz/32), 256>>>(v, vt);
    softmax_kernel<<<BHz*Sz, 256>>>(sc, rs);
    tf32_ctx<<<dim3(1, Sz/128, BHz), 256, SMEM_BYTES>>>(sc, vt, rs, ctx);
    tf32_gemm_nt<<<dim3(Dz/128, NTz/128), 256, SMEM_BYTES>>>(ctx, wr+WR_O, h2, nullptr, x, NTz, Dz, Dz);

    // --- MoE block --- (q buffer reused as fp32 h3 for the router)
    rmsnorm_kernel<<<NTz, 256>>>(h2, ln2w, h1, q);
    router_kernel<<<NTz, 256>>>(q, rw, rb, choice);

    tf32_gemm_nt<<<dim3(Fz/128, NTz/128), 256, SMEM_BYTES>>>(h1, wr+WR_E1G, gate, nullptr, nullptr, NTz, Fz, Dz);
    tf32_gemm_nt<<<dim3(Fz/128, NTz/128), 256, SMEM_BYTES>>>(h1, wr+WR_E1U, up,   nullptr, nullptr, NTz, Fz, Dz);
    act_kernel<<<dim3((Fz+255)/256, NTz), 256>>>(gate, up, choice, 0);
    tf32_gemm_nt<<<dim3(Dz/128, NTz/128), 256, SMEM_BYTES>>>(gate, wr+WR_E1D, out, nullptr, h2, NTz, Dz, Fz);

    tf32_gemm_nt<<<dim3(Fz/128, NTz/128), 256, SMEM_BYTES>>>(h1, wr+WR_E2G, gate, nullptr, nullptr, NTz, Fz, Dz);
    tf32_gemm_nt<<<dim3(Fz/128, NTz/128), 256, SMEM_BYTES>>>(h1, wr+WR_E2U, up,   nullptr, nullptr, NTz, Fz, Dz);
    act_kernel<<<dim3((Fz+255)/256, NTz), 256>>>(gate, up, choice, 1);
    tf32_gemm_nt<<<dim3(Dz/128, NTz/128), 256, SMEM_BYTES>>>(gate, wr+WR_E2D, out, nullptr, out, NTz, Dz, Fz);
}

// round 12
// speedup vs baseline: 2.1449x; 1.8525x over previous
#include <cuda_runtime.h>
#include <cuda_fp16.h>
#include <math.h>
#include <stdint.h>

#define Bz   2
#define Sz   2048
#define Dz   2048
#define Hz   16
#define DHz  128
#define Fz   5504
#define NTz  (Bz*Sz)      // 4096 tokens
#define BHz  (Bz*Hz)      // 32
#define ATTN_SCALE 0.08838834764831845f   // 1/sqrt(128)

// ---------------- scratch (device globals; allocation-free) ----------------
__device__ __half g_h1h [(size_t)NTz*Dz];     // rmsnorm out (fp16)
__device__ __half g_qh  [(size_t)NTz*Dz];
__device__ __half g_kh  [(size_t)NTz*Dz];     // k; later vt (transposed V)
__device__ __half g_vh  [(size_t)NTz*Dz];
__device__ __half g_ctxh[(size_t)NTz*Dz];
__device__ float  g_h2  [(size_t)NTz*Dz];     // attn residual (fp32)
__device__ float  g_sc  [(size_t)BHz*Sz*Sz];  // fp32 logits; later fp32 raw h3 for router
__device__ __half g_ph  [(size_t)BHz*Sz*Sz];  // fp16 probs
__device__ float  g_rs  [(size_t)BHz*Sz];
__device__ __half g_gateh[(size_t)NTz*Fz];
__device__ __half g_uph  [(size_t)NTz*Fz];
__device__ int    g_choice[NTz];
// pre-rounded fp16 weights
#define WR_Q   0
#define WR_K   4194304
#define WR_V   8388608
#define WR_O   12582912
#define WR_E1G 16777216
#define WR_E1U 28049408
#define WR_E1D 39321600
#define WR_E2G 50593792
#define WR_E2U 61865984
#define WR_E2D 73138176
#define WR_TOT 84410368
__device__ __half g_wrh[(size_t)WR_TOT];

// ================= FP16 MMA machinery =================
// Block tile 128x128x32, 256 threads, warp tile 32(M)x64(N).
// Operands fp16 in smem [row][k] pitch 40 halfs; mma.sync.m16n8k16 fp32 acc.
// Virtual-K bijection: chunk c, thread tg, pos p  <->  phys k = tg*8+c*4+p,
// applied identically to A and B -> exact dot product.
// 3-stage cp.async ring, one __syncthreads per K-iter.

#define PITCH_H 40
#define A_HALFS (128*PITCH_H)          // 5120 halfs
#define STAGE_H (2*A_HALFS)            // 10240 halfs = 20480 B
#define NSTAGE 3
#define SMEM_BYTES (NSTAGE*STAGE_H*2)  // 61440 B

__device__ __forceinline__ unsigned sptr(const void* p){ return (unsigned)__cvta_generic_to_shared(p); }
__device__ __forceinline__ void cpa16(unsigned s, const void* g){
    asm volatile("cp.async.cg.shared.global [%0], [%1], 16;\n" :: "r"(s), "l"(g));
}
__device__ __forceinline__ void cpcommit(){ asm volatile("cp.async.commit_group;\n" ::); }
__device__ __forceinline__ void cpwait1(){ asm volatile("cp.async.wait_group 1;\n" ::); }
__device__ __forceinline__ void mma16816(float* c, unsigned a0,unsigned a1,unsigned a2,unsigned a3,
                                         unsigned b0, unsigned b1){
    asm volatile("mma.sync.aligned.m16n8k16.row.col.f32.f16.f16.f32 "
                 "{%0,%1,%2,%3},{%4,%5,%6,%7},{%8,%9},{%0,%1,%2,%3};\n"
                 : "+f"(c[0]),"+f"(c[1]),"+f"(c[2]),"+f"(c[3])
                 : "r"(a0),"r"(a1),"r"(a2),"r"(a3),"r"(b0),"r"(b1));
}

// load 128 rows x 32 k-halfs (64B/row) into smem [row][k] pitch 40 halfs
__device__ __forceinline__ void load_tile16(__half* S, const __half* G, int ld, int tid){
    const int r = tid >> 1, cb = (tid & 1) * 16;          // halfs
    const __half* g = G + (size_t)r * ld + cb;
    unsigned s = sptr(S) + (unsigned)(r * PITCH_H + cb) * 2u;
    cpa16(s, g);
    cpa16(s + 16u, g + 8);
}

__device__ __forceinline__ void compute16(const __half* __restrict__ As, const __half* __restrict__ Bs,
                                          float acc[2][8][4], int warpM, int warpN, int lane){
    const int gi = lane >> 2, tg = lane & 3;
    const int r0 = warpM*32 + gi;
    unsigned a[4][4];
    #pragma unroll
    for (int r = 0; r < 4; r++)
        *(uint4*)a[r] = *(const uint4*)(As + (r0 + r*8)*PITCH_H + tg*8);
    #pragma unroll
    for (int j = 0; j < 8; j++){
        unsigned b[4];
        *(uint4*)b = *(const uint4*)(Bs + (warpN*64 + j*8 + gi)*PITCH_H + tg*8);
        #pragma unroll
        for (int c = 0; c < 2; c++){
            mma16816(acc[0][j], a[0][2*c], a[1][2*c], a[0][2*c+1], a[1][2*c+1], b[2*c], b[2*c+1]);
            mma16816(acc[1][j], a[2][2*c], a[3][2*c], a[2][2*c+1], a[3][2*c+1], b[2*c], b[2*c+1]);
        }
    }
}

// 3-stage ring mainloop: compute buf t%3, prefetch buf (t+2)%3, one sync/iter.
__device__ __forceinline__ void mainloop16(__half* sm, const __half* Ag, int lda,
                                           const __half* Bg, int ldb, int T,
                                           float acc[2][8][4], int warpM, int warpN, int lane, int tid){
    load_tile16(sm, Ag, lda, tid);
    load_tile16(sm + A_HALFS, Bg, ldb, tid);
    cpcommit();
    load_tile16(sm + STAGE_H, Ag + 32, lda, tid);
    load_tile16(sm + STAGE_H + A_HALFS, Bg + 32, ldb, tid);
    cpcommit();
    for (int t = 0; t < T; t++){
        cpwait1();
        __syncthreads();
        const int u = t + 2;
        if (u < T){
            __half* Sd = sm + (u % NSTAGE) * STAGE_H;
            load_tile16(Sd, Ag + u*32, lda, tid);
            load_tile16(Sd + A_HALFS, Bg + u*32, ldb, tid);
        }
        cpcommit();
        const __half* Sa = sm + (t % NSTAGE) * STAGE_H;
        compute16(Sa, Sa + A_HALFS, acc, warpM, warpN, lane);
    }
}

#define ACC_INIT() float acc[2][8][4]; \
    _Pragma("unroll") for (int i=0;i<2;i++) \
    _Pragma("unroll") for (int j=0;j<8;j++) \
    _Pragma("unroll") for (int c=0;c<4;c++) acc[i][j][c]=0.f;

extern __shared__ __half smemh[];

// ---------- NT GEMM, fp16 out (+bias): C[M,N] = A[M,K]*B[N,K]^T ----------
__global__ __launch_bounds__(256, 2) void h16_gemm_f16out(
    const __half* __restrict__ A, const __half* __restrict__ B,
    __half* __restrict__ C, const float* __restrict__ bias, int M, int N, int K)
{
    const int tid = threadIdx.x, lane = tid & 31, warp = tid >> 5;
    const int warpM = warp & 3, warpN = warp >> 2;
    const int bm = blockIdx.y, bn = blockIdx.x;
    ACC_INIT();
    mainloop16(smemh, A + (size_t)bm*128*K, K, B + (size_t)bn*128*K, K, K/32,
               acc, warpM, warpN, lane, tid);
    const int gi = lane >> 2, tg = lane & 3;
    #pragma unroll
    for (int i = 0; i < 2; i++){
        const int row = bm*128 + warpM*32 + i*16 + gi;
        #pragma unroll
        for (int j = 0; j < 8; j++){
            const int col = bn*128 + warpN*64 + j*8 + tg*2;
            float v0 = acc[i][j][0], v1 = acc[i][j][1];
            float w0 = acc[i][j][2], w1 = acc[i][j][3];
            if (bias){
                const float b0 = bias[col], b1 = bias[col+1];
                v0 += b0; v1 += b1; w0 += b0; w1 += b1;
            }
            *(half2*)&C[(size_t)row * N + col]     = __floats2half2_rn(v0, v1);
            *(half2*)&C[(size_t)(row+8) * N + col] = __floats2half2_rn(w0, w1);
        }
    }
}

// ---------- NT GEMM, fp32 out (+add): C = A*B^T + add ----------
__global__ __launch_bounds__(256, 2) void h16_gemm_f32out(
    const __half* __restrict__ A, const __half* __restrict__ B,
    float* __restrict__ C, const float* __restrict__ add, int M, int N, int K)
{
    const int tid = threadIdx.x, lane = tid & 31, warp = tid >> 5;
    const int warpM = warp & 3, warpN = warp >> 2;
    const int bm = blockIdx.y, bn = blockIdx.x;
    ACC_INIT();
    mainloop16(smemh, A + (size_t)bm*128*K, K, B + (size_t)bn*128*K, K, K/32,
               acc, warpM, warpN, lane, tid);
    const int gi = lane >> 2, tg = lane & 3;
    #pragma unroll
    for (int i = 0; i < 2; i++){
        const int row = bm*128 + warpM*32 + i*16 + gi;
        #pragma unroll
        for (int j = 0; j < 8; j++){
            const int col = bn*128 + warpN*64 + j*8 + tg*2;
            float2 v0 = make_float2(acc[i][j][0], acc[i][j][1]);
            float2 v1 = make_float2(acc[i][j][2], acc[i][j][3]);
            float2 r0 = *(const float2*)&add[(size_t)row * N + col];
            float2 r1 = *(const float2*)&add[(size_t)(row+8) * N + col];
            v0.x += r0.x; v0.y += r0.y; v1.x += r1.x; v1.y += r1.y;
            *(float2*)&C[(size_t)row * N + col]     = v0;
            *(float2*)&C[(size_t)(row+8) * N + col] = v1;
        }
    }
}

// ---------- attention scores: fp32 logits, causal (masked blocks skipped) ----------
__global__ __launch_bounds__(256, 2) void h16_scores(
    const __half* __restrict__ Q, const __half* __restrict__ Km, float* __restrict__ Sc)
{
    const int bm = blockIdx.y, bn = blockIdx.x;
    if (bn > bm) return;   // never read downstream
    const int z = blockIdx.z, b = z >> 4, h = z & 15;
    const int tid = threadIdx.x, lane = tid & 31, warp = tid >> 5;
    const int warpM = warp & 3, warpN = warp >> 2;
    float* Cb = Sc + (size_t)z * Sz * Sz;
    const __half* Ag = Q  + (size_t)(b*Sz + bm*128) * Dz + (size_t)h * DHz;
    const __half* Bg = Km + (size_t)(b*Sz + bn*128) * Dz + (size_t)h * DHz;
    ACC_INIT();
    mainloop16(smemh, Ag, Dz, Bg, Dz, DHz/32, acc, warpM, warpN, lane, tid);
    const int gi = lane >> 2, tg = lane & 3;
    #pragma unroll
    for (int i = 0; i < 2; i++){
        const int row0 = bm*128 + warpM*32 + i*16 + gi;
        #pragma unroll
        for (int j = 0; j < 8; j++){
            const int col = bn*128 + warpN*64 + j*8 + tg*2;
            float2 v0, v1;
            v0.x = (col   <= row0  ) ? acc[i][j][0]*ATTN_SCALE : -1e30f;
            v0.y = (col+1 <= row0  ) ? acc[i][j][1]*ATTN_SCALE : -1e30f;
            v1.x = (col   <= row0+8) ? acc[i][j][2]*ATTN_SCALE : -1e30f;
            v1.y = (col+1 <= row0+8) ? acc[i][j][3]*ATTN_SCALE : -1e30f;
            *(float2*)&Cb[(size_t)row0 * Sz + col]     = v0;
            *(float2*)&Cb[(size_t)(row0+8) * Sz + col] = v1;
        }
    }
}

// ---------- attention ctx: Cx = P Vt^T, causal K-trim, normalized, fp16 out ----------
__global__ __launch_bounds__(256, 2) void h16_ctx(
    const __half* __restrict__ P, const __half* __restrict__ Vt,
    const float* __restrict__ rowsum, __half* __restrict__ Cx)
{
    const int z = blockIdx.z, b = z >> 4, h = z & 15;
    const int bm = blockIdx.y;
    const int tid = threadIdx.x, lane = tid & 31, warp = tid >> 5;
    const int warpM = warp & 3, warpN = warp >> 2;
    const __half* Ag = P  + (size_t)z * Sz * Sz + (size_t)bm * 128 * Sz;
    const __half* Bg = Vt + (size_t)z * 128 * Sz;
    ACC_INIT();
    mainloop16(smemh, Ag, Sz, Bg, Sz, (bm + 1) * 4, acc, warpM, warpN, lane, tid);
    const int gi = lane >> 2, tg = lane & 3;
    #pragma unroll
    for (int i = 0; i < 2; i++){
        const int rloc = bm*128 + warpM*32 + i*16 + gi;
        const float inv0 = 1.f / rowsum[(size_t)z * Sz + rloc];
        const float inv1 = 1.f / rowsum[(size_t)z * Sz + rloc + 8];
        const size_t row0 = (size_t)(b*Sz) + rloc;
        #pragma unroll
        for (int j = 0; j < 8; j++){
            const int col = h*DHz + warpN*64 + j*8 + tg*2;
            *(half2*)&Cx[row0 * Dz + col]     = __floats2half2_rn(acc[i][j][0]*inv0, acc[i][j][1]*inv0);
            *(half2*)&Cx[(row0+8) * Dz + col] = __floats2half2_rn(acc[i][j][2]*inv1, acc[i][j][3]*inv1);
        }
    }
}

// ================= helpers / elementwise =================
__global__ __launch_bounds__(256) void h16_round(
    const float* __restrict__ src, __half* __restrict__ dst, int n8)
{
    const int i = blockIdx.x * 256 + threadIdx.x;
    if (i >= n8) return;
    float4 v0 = ((const float4*)src)[2*(size_t)i];
    float4 v1 = ((const float4*)src)[2*(size_t)i + 1];
    half2 h0 = __floats2half2_rn(v0.x, v0.y), h1 = __floats2half2_rn(v0.z, v0.w);
    half2 h2 = __floats2half2_rn(v1.x, v1.y), h3 = __floats2half2_rn(v1.z, v1.w);
    uint4 u;
    u.x = *(unsigned*)&h0; u.y = *(unsigned*)&h1;
    u.z = *(unsigned*)&h2; u.w = *(unsigned*)&h3;
    ((uint4*)dst)[i] = u;
}

// transpose vh[token][Dz] -> vt[(b*16+h)*128+dh][token_in_batch]
__global__ __launch_bounds__(256) void transpose_v16(const __half* __restrict__ v, __half* __restrict__ vt)
{
    __shared__ unsigned short tile[32][33];
    const int tid = threadIdx.x;
    const int d0 = blockIdx.x * 32, t0 = blockIdx.y * 32;
    const int tx = tid & 31, ty = tid >> 5;
    #pragma unroll
    for (int it = 0; it < 4; it++){
        const int tok = t0 + ty + it*8;
        tile[ty + it*8][tx] = *(const unsigned short*)&v[(size_t)tok * Dz + d0 + tx];
    }
    __syncthreads();
    #pragma unroll
    for (int it = 0; it < 4; it++){
        const int dh_loc = ty + it*8;
        const int gd = d0 + dh_loc;
        const int tok = t0 + tx;
        const int bb = tok >> 11, tin = tok & 2047;
        *(unsigned short*)&vt[((size_t)(bb*16) * 128 + gd) * Sz + tin] = tile[tx][dh_loc];
    }
}

__global__ __launch_bounds__(256) void rmsnorm_kernel(
    const float* __restrict__ x, const float* __restrict__ w,
    __half* __restrict__ out, float* __restrict__ out_raw)
{
    const int row = blockIdx.x;
    const float* xr = x + (size_t)row * Dz;
    __half* orow = out + (size_t)row * Dz;
    const int tid = threadIdx.x;
    float ss = 0.f;
    #pragma unroll
    for (int i = tid*4; i < Dz; i += 1024) {
        float4 v = *(const float4*)(xr + i);
        ss += v.x*v.x + v.y*v.y + v.z*v.z + v.w*v.w;
    }
    __shared__ float red[256];
    red[tid] = ss; __syncthreads();
    for (int s = 128; s > 0; s >>= 1) { if (tid < s) red[tid] += red[tid+s]; __syncthreads(); }
    const float scale = rsqrtf(red[0] / (float)Dz + 1e-6f);
    #pragma unroll
    for (int i = tid*4; i < Dz; i += 1024) {
        float4 v = *(const float4*)(xr + i);
        float4 ww = *(const float4*)(w + i);
        float4 o;
        o.x = v.x*scale*ww.x; o.y = v.y*scale*ww.y;
        o.z = v.z*scale*ww.z; o.w = v.w*scale*ww.w;
        if (out_raw) *(float4*)(out_raw + (size_t)row * Dz + i) = o;
        *(half2*)(orow + i)     = __floats2half2_rn(o.x, o.y);
        *(half2*)(orow + i + 2) = __floats2half2_rn(o.z, o.w);
    }
}

__global__ __launch_bounds__(256) void rope_kernel16(__half* __restrict__ q, __half* __restrict__ k)
{
    const size_t idx = (size_t)blockIdx.x * 256 + threadIdx.x;
    if (idx >= (size_t)NTz * Hz * 64) return;
    const int    j    = (int)(idx & 63);
    const size_t th   = idx >> 6;
    const int    head = (int)(th & 15);
    const size_t tok  = th >> 4;
    const int    s    = (int)(tok & (Sz - 1));
    const double inv  = exp(-(double)(2*j) / 128.0 * 9.210340371976184);
    const double ang  = (double)s * inv;
    const float  c  = (float)cos(ang);
    const float  sn = (float)sin(ang);
    const size_t base = tok * (size_t)Dz + (size_t)head * DHz + j;
    float q1 = __half2float(q[base]), q2 = __half2float(q[base + 64]);
    q[base]      = __float2half_rn(q1*c - q2*sn);
    q[base + 64] = __float2half_rn(q2*c + q1*sn);
    float k1 = __half2float(k[base]), k2 = __half2float(k[base + 64]);
    k[base]      = __float2half_rn(k1*c - k2*sn);
    k[base + 64] = __float2half_rn(k2*c + k1*sn);
}

// causal softmax: fp32 logits -> fp16 probs + fp32 rowsum (of rounded probs)
__global__ __launch_bounds__(256) void softmax_kernel16(
    const float* __restrict__ Sc, __half* __restrict__ Ph, float* __restrict__ rowsum)
{
    const size_t row = blockIdx.x;
    const int sloc = (int)(row & (Sz - 1));
    const int len = ((sloc >> 7) + 1) << 7;
    const float* p = Sc + row * (size_t)Sz;
    __half* o = Ph + row * (size_t)Sz;
    const int tid = threadIdx.x;
    float m = -1e30f;
    for (int i = tid*4; i < len; i += 1024) {
        float4 v = *(const float4*)(p + i);
        m = fmaxf(m, fmaxf(fmaxf(v.x, v.y), fmaxf(v.z, v.w)));
    }
    __shared__ float red[256];
    red[tid] = m; __syncthreads();
    for (int s = 128; s > 0; s >>= 1) { if (tid < s) red[tid] = fmaxf(red[tid], red[tid+s]); __syncthreads(); }
    m = red[0];
    __syncthreads();
    float sum = 0.f;
    for (int i = tid*4; i < len; i += 1024) {
        float4 v = *(const float4*)(p + i);
        __half e0 = __float2half_rn(expf(v.x - m));
        __half e1 = __float2half_rn(expf(v.y - m));
        __half e2 = __float2half_rn(expf(v.z - m));
        __half e3 = __float2half_rn(expf(v.w - m));
        sum += __half2float(e0) + __half2float(e1) + __half2float(e2) + __half2float(e3);
        half2 ha; ha.x = e0; ha.y = e1;
        half2 hb; hb.x = e2; hb.y = e3;
        *(half2*)(o + i)     = ha;
        *(half2*)(o + i + 2) = hb;
    }
    red[tid] = sum; __syncthreads();
    for (int s = 128; s > 0; s >>= 1) { if (tid < s) red[tid] += red[tid+s]; __syncthreads(); }
    if (tid == 0) rowsum[row] = red[0];
}

__global__ __launch_bounds__(256) void router_kernel(
    const float* __restrict__ h, const float* __restrict__ rw,
    const float* __restrict__ rb, int* __restrict__ choice)
{
    const int t = blockIdx.x;
    const float* xr = h + (size_t)t * Dz;
    const int tid = threadIdx.x;
    float s0 = 0.f, s1 = 0.f;
    #pragma unroll
    for (int i = tid*4; i < Dz; i += 1024) {
        float4 v  = *(const float4*)(xr + i);
        float4 w0 = *(const float4*)(rw + i);
        float4 w1 = *(const float4*)(rw + Dz + i);
        s0 += v.x*w0.x + v.y*w0.y + v.z*w0.z + v.w*w0.w;
        s1 += v.x*w1.x + v.y*w1.y + v.z*w1.z + v.w*w1.w;
    }
    __shared__ float r0[256], r1[256];
    r0[tid] = s0; r1[tid] = s1; __syncthreads();
    for (int s = 128; s > 0; s >>= 1) {
        if (tid < s) { r0[tid] += r0[tid+s]; r1[tid] += r1[tid+s]; }
        __syncthreads();
    }
    if (tid == 0) {
        const float l0 = r0[0] + rb[0], l1 = r1[0] + rb[1];
        choice[t] = (l1 > l0) ? 1 : 0;
    }
}

__global__ __launch_bounds__(256) void act_kernel16(
    __half* __restrict__ gate, const __half* __restrict__ up,
    const int* __restrict__ choice, int e)
{
    const int f = blockIdx.x * 256 + threadIdx.x;
    if (f >= Fz) return;
    const int tok = blockIdx.y;
    const size_t idx = (size_t)tok * Fz + f;
    if (choice[tok] == e) {
        const float g = __half2float(gate[idx]);
        const float u = __half2float(up[idx]);
        gate[idx] = __float2half_rn((g / (1.f + expf(-g))) * u);
    } else {
        gate[idx] = __float2half_rn(0.f);
    }
}

// ================= launch =================
extern "C" void kernel_launch(void* const* d_in, const int* in_sizes, int n_in,
                              void* d_out, int out_size)
{
    const float* x    = (const float*)d_in[0];
    const float* ln1w = (const float*)d_in[1];
    const float* wq   = (const float*)d_in[2];
    const float* bq   = (const float*)d_in[3];
    const float* wk   = (const float*)d_in[4];
    const float* bk   = (const float*)d_in[5];
    const float* wv   = (const float*)d_in[6];
    const float* bv   = (const float*)d_in[7];
    const float* wo   = (const float*)d_in[8];
    const float* ln2w = (const float*)d_in[9];
    const float* e1g  = (const float*)d_in[10];
    const float* e1u  = (const float*)d_in[11];
    const float* e1d  = (const float*)d_in[12];
    const float* e2g  = (const float*)d_in[13];
    const float* e2u  = (const float*)d_in[14];
    const float* e2d  = (const float*)d_in[15];
    const float* rw   = (const float*)d_in[16];
    const float* rb   = (const float*)d_in[17];
    float* out = (float*)d_out;

    __half *h1h, *qh, *kh, *vh, *ctxh, *ph, *gateh, *uph, *wrh;
    float *h2, *sc, *rs;
    int* choice;
    cudaGetSymbolAddress((void**)&h1h,  g_h1h);
    cudaGetSymbolAddress((void**)&qh,   g_qh);
    cudaGetSymbolAddress((void**)&kh,   g_kh);
    cudaGetSymbolAddress((void**)&vh,   g_vh);
    cudaGetSymbolAddress((void**)&ctxh, g_ctxh);
    cudaGetSymbolAddress((void**)&h2,   g_h2);
    cudaGetSymbolAddress((void**)&sc,   g_sc);
    cudaGetSymbolAddress((void**)&ph,   g_ph);
    cudaGetSymbolAddress((void**)&rs,   g_rs);
    cudaGetSymbolAddress((void**)&gateh, g_gateh);
    cudaGetSymbolAddress((void**)&uph,   g_uph);
    cudaGetSymbolAddress((void**)&wrh,   g_wrh);
    cudaGetSymbolAddress((void**)&choice, g_choice);

    cudaFuncSetAttribute(h16_gemm_f16out, cudaFuncAttributeMaxDynamicSharedMemorySize, SMEM_BYTES);
    cudaFuncSetAttribute(h16_gemm_f32out, cudaFuncAttributeMaxDynamicSharedMemorySize, SMEM_BYTES);
    cudaFuncSetAttribute(h16_scores,      cudaFuncAttributeMaxDynamicSharedMemorySize, SMEM_BYTES);
    cudaFuncSetAttribute(h16_ctx,         cudaFuncAttributeMaxDynamicSharedMemorySize, SMEM_BYTES);

    // --- weight pre-rounding (fp16) ---
    #define RND(src, off, n) h16_round<<<((n)/8+255)/256, 256>>>(src, wrh + (size_t)(off), (n)/8)
    RND(wq,  WR_Q,   Dz*Dz);  RND(wk,  WR_K,   Dz*Dz);
    RND(wv,  WR_V,   Dz*Dz);  RND(wo,  WR_O,   Dz*Dz);
    RND(e1g, WR_E1G, Fz*Dz);  RND(e1u, WR_E1U, Fz*Dz);  RND(e1d, WR_E1D, Fz*Dz);
    RND(e2g, WR_E2G, Fz*Dz);  RND(e2u, WR_E2U, Fz*Dz);  RND(e2d, WR_E2D, Fz*Dz);
    #undef RND

    // --- attention block ---
    rmsnorm_kernel<<<NTz, 256>>>(x, ln1w, h1h, nullptr);
    h16_gemm_f16out<<<dim3(Dz/128, NTz/128), 256, SMEM_BYTES>>>(h1h, wrh+WR_Q, qh, bq, NTz, Dz, Dz);
    h16_gemm_f16out<<<dim3(Dz/128, NTz/128), 256, SMEM_BYTES>>>(h1h, wrh+WR_K, kh, bk, NTz, Dz, Dz);
    h16_gemm_f16out<<<dim3(Dz/128, NTz/128), 256, SMEM_BYTES>>>(h1h, wrh+WR_V, vh, bv, NTz, Dz, Dz);
    rope_kernel16<<<(NTz*Hz*64)/256, 256>>>(qh, kh);
    h16_scores<<<dim3(Sz/128, Sz/128, BHz), 256, SMEM_BYTES>>>(qh, kh, sc);
    __half* vt = kh;   // kh's memory reused as transposed V after scores consumed it
    transpose_v16<<<dim3(Dz/32, NTz/32), 256>>>(vh, vt);
    softmax_kernel16<<<BHz*Sz, 256>>>(sc, ph, rs);
    h16_ctx<<<dim3(1, Sz/128, BHz), 256, SMEM_BYTES>>>(ph, vt, rs, ctxh);
    h16_gemm_f32out<<<dim3(Dz/128, NTz/128), 256, SMEM_BYTES>>>(ctxh, wrh+WR_O, h2, x, NTz, Dz, Dz);

    // --- MoE block --- (g_sc region reused as fp32 raw h3 for the router)
    float* h3raw = sc;
    rmsnorm_kernel<<<NTz, 256>>>(h2, ln2w, h1h, h3raw);
    router_kernel<<<NTz, 256>>>(h3raw, rw, rb, choice);

    h16_gemm_f16out<<<dim3(Fz/128, NTz/128), 256, SMEM_BYTES>>>(h1h, wrh+WR_E1G, gateh, nullptr, NTz, Fz, Dz);
    h16_gemm_f16out<<<dim3(Fz/128, NTz/128), 256, SMEM_BYTES>>>(h1h, wrh+WR_E1U, uph,   nullptr, NTz, Fz, Dz);
    act_kernel16<<<dim3((Fz+255)/256, NTz), 256>>>(gateh, uph, choice, 0);
    h16_gemm_f32out<<<dim3(Dz/128, NTz/128), 256, SMEM_BYTES>>>(gateh, wrh+WR_E1D, out, h2, NTz, Dz, Fz);

    h16_gemm_f16out<<<dim3(Fz/128, NTz/128), 256, SMEM_BYTES>>>(h1h, wrh+WR_E2G, gateh, nullptr, NTz, Fz, Dz);
    h16_gemm_f16out<<<dim3(Fz/128, NTz/128), 256, SMEM_BYTES>>>(h1h, wrh+WR_E2U, uph,   nullptr, NTz, Fz, Dz);
    act_kernel16<<<dim3((Fz+255)/256, NTz), 256>>>(gateh, uph, choice, 1);
    h16_gemm_f32out<<<dim3(Dz/128, NTz/128), 256, SMEM_BYTES>>>(gateh, wrh+WR_E2D, out, out, NTz, Dz, Fz);
}